// round 9
// baseline (speedup 1.0000x reference)
#include <cuda_runtime.h>
#include <cuda.h>
#include <cuda_bf16.h>
#include <cstdint>
#include <math.h>

#define DEV_INLINE __device__ __forceinline__

// Does this compilation pass target sm_103a (arch-specific features available)?
#ifdef __CUDA_ARCH_FEAT_SM103_ALL
#define USE_TC 1
#else
#define USE_TC 0
#endif

// ---------------- problem constants ----------------
#define B_DIM 4096          // batch rows (GEMM M)
#define K_DIM 2048          // inner dim  (GEMM K)
#define M_DIM 2048          // out cols   (GEMM N)

// ---------------- GEMM tiling (both paths: CTA covers 128 x 256) ----------------
#define BM 128
#define BN 256
#define THREADS 512
#define CLUSTER_SZ 8        // 4 tileM x 2 tileN; A multicast x2, B multicast x4

// ---- tcgen05 path smem: 4-stage ring, BK=32 (SW64, 64B rows) ----
#define SMEM_TMEM_PTR 0
#define SMEM_FULL(s)  (8 + (s) * 8)            // 4 full barriers
#define SMEM_DONE(s)  (40 + (s) * 8)           // 4 done barriers
#define SMEM_FINAL    72
#define TILE_BASE     1024
#define TC_BK         32
#define TC_NT         (K_DIM / TC_BK)          // 64
#define NSTAGE        4
#define STG_A         0                        // Ah (8KB)
#define STG_AL        8192                     // Al (8KB)
#define STG_BH        16384                    // Bh (four 4KB quarter slices)
#define STG_BL        32768                    // Bl (four 4KB quarter slices)
#define STAGE_BYTES   49152                    // 48KB
#define SMEM_TOTAL    (TILE_BASE + NSTAGE * STAGE_BYTES)   // 197632

// ---- hmma fallback smem (compile-legality for the compute_103 PTX pass) ----
#define MM_BK         32
#define MM_NT         (K_DIM / MM_BK)              // 64
#define MM_ROWB       80                           // 64B row + 16B pad
#define MM_A_BYTES    (BM * MM_ROWB)               // 10240
#define MM_B_BYTES    (BN * MM_ROWB)               // 20480
#define MM_STAGE      (2 * MM_A_BYTES + 2 * MM_B_BYTES)  // 61440
#define MM_STAGES     3

// ---------------- device scratch (allocation-free rule: __device__ globals) ----------------
__device__ __align__(16) __nv_bfloat16 g_xh[(long)B_DIM * K_DIM];
__device__ __align__(16) __nv_bfloat16 g_xl[(long)B_DIM * K_DIM];
__device__ __align__(16) __nv_bfloat16 g_wh[(long)M_DIM * K_DIM];   // [j][k] (transposed W)
__device__ __align__(16) __nv_bfloat16 g_wl[(long)M_DIM * K_DIM];
__device__ float g_bias[M_DIM];                                     // classical_bias + probs

// ---------------- PTX helpers (base-arch legal) ----------------
DEV_INLINE uint32_t smem_u32(const void* p) {
    uint32_t a;
    asm("{ .reg .u64 t; cvta.to.shared.u64 t, %1; cvt.u32.u64 %0, t; }" : "=r"(a) : "l"(p));
    return a;
}

DEV_INLINE void cp16(uint32_t dst, const void* src) {
    asm volatile("cp.async.cg.shared.global [%0], [%1], 16;" :: "r"(dst), "l"(src) : "memory");
}
DEV_INLINE void cp_commit() { asm volatile("cp.async.commit_group;" ::: "memory"); }

DEV_INLINE void ldsm4(uint32_t* r, uint32_t addr) {
    asm volatile("ldmatrix.sync.aligned.m8n8.x4.shared.b16 {%0,%1,%2,%3}, [%4];"
                 : "=r"(r[0]), "=r"(r[1]), "=r"(r[2]), "=r"(r[3]) : "r"(addr));
}
DEV_INLINE void mma16816(float* c, const uint32_t* a, uint32_t b0, uint32_t b1) {
    asm volatile("mma.sync.aligned.m16n8k16.row.col.f32.bf16.bf16.f32 "
                 "{%0,%1,%2,%3}, {%4,%5,%6,%7}, {%8,%9}, {%0,%1,%2,%3};"
                 : "+f"(c[0]), "+f"(c[1]), "+f"(c[2]), "+f"(c[3])
                 : "r"(a[0]), "r"(a[1]), "r"(a[2]), "r"(a[3]), "r"(b0), "r"(b1));
}

#if USE_TC
// ---------------- tcgen05 / TMA helpers (only in the sm_103a pass) ----------------
DEV_INLINE uint32_t elect_one() {
    uint32_t pred;
    asm volatile("{\n\t.reg .pred p;\n\telect.sync _|p, 0xFFFFFFFF;\n\t"
                 "selp.b32 %0, 1, 0, p;\n\t}" : "=r"(pred));
    return pred;
}
DEV_INLINE uint32_t ctarank() {
    uint32_t r;
    asm("mov.u32 %0, %%cluster_ctarank;" : "=r"(r));
    return r;
}
#define MBAR_INIT(addr, cnt) \
    asm volatile("mbarrier.init.shared.b64 [%0], %1;" :: "r"(addr), "r"(cnt) : "memory")
#define MBAR_INVAL(addr) \
    asm volatile("mbarrier.inval.shared.b64 [%0];" :: "r"(addr) : "memory")
#define MBAR_EXPECT_TX(addr, tx) \
    asm volatile("mbarrier.arrive.expect_tx.shared.b64 _, [%0], %1;" \
                 :: "r"(addr), "r"((uint32_t)(tx)) : "memory")
#define CLUSTER_SYNC() do { \
    asm volatile("barrier.cluster.arrive.aligned;" ::: "memory"); \
    asm volatile("barrier.cluster.wait.aligned;" ::: "memory"); \
} while (0)

DEV_INLINE void mbar_wait(uint32_t mbar, uint32_t parity) {
    uint32_t done;
    asm volatile("{\n\t.reg .pred p;\n\t"
                 "mbarrier.try_wait.parity.acquire.cta.shared::cta.b64 p, [%1], %2;\n\t"
                 "selp.b32 %0, 1, 0, p;\n\t}"
                 : "=r"(done) : "r"(mbar), "r"(parity) : "memory");
    if (!done) {
        asm volatile("{\n\t.reg .pred P1;\n\t"
                     "W_%=:\n\t"
                     "mbarrier.try_wait.parity.acquire.cta.shared::cta.b64 P1, [%0], %1, 0x989680;\n\t"
                     "@P1 bra.uni D_%=;\n\t"
                     "bra.uni W_%=;\n\t"
                     "D_%=:\n\t}"
                     :: "r"(mbar), "r"(parity) : "memory");
    }
}

#define TCGEN05_ALLOC(sm_addr, nc) \
    asm volatile("tcgen05.alloc.cta_group::1.sync.aligned.shared::cta.b32 [%0], %1;" \
                 :: "r"((uint32_t)(sm_addr)), "r"((uint32_t)(nc)) : "memory")
#define TCGEN05_DEALLOC(tmem, nc) \
    asm volatile("tcgen05.dealloc.cta_group::1.sync.aligned.b32 %0, %1;" :: "r"(tmem), "r"(nc))
#define TCGEN05_COMMIT(mbar) \
    asm volatile("tcgen05.commit.cta_group::1.mbarrier::arrive::one.shared::cluster.b64 [%0];" \
                 :: "r"((uint32_t)(mbar)) : "memory")
#define TCGEN05_COMMIT_MC(mbar, mask) \
    asm volatile("tcgen05.commit.cta_group::1.mbarrier::arrive::one.shared::cluster.multicast::cluster.b64 [%0], %1;" \
                 :: "r"((uint32_t)(mbar)), "h"((uint16_t)(mask)) : "memory")
#define TCGEN05_FENCE_AFTER()  asm volatile("tcgen05.fence::after_thread_sync;" ::: "memory")
#define TCGEN05_FENCE_BEFORE() asm volatile("tcgen05.fence::before_thread_sync;" ::: "memory")
#define TCGEN05_WAIT_LD()      asm volatile("tcgen05.wait::ld.sync.aligned;" ::: "memory")

#define TCGEN05_LD_X32(r, ta) \
    asm volatile("tcgen05.ld.sync.aligned.32x32b.x32.b32 " \
        "{%0, %1, %2, %3, %4, %5, %6, %7, %8, %9, %10, %11, %12, %13, %14, %15, " \
        " %16, %17, %18, %19, %20, %21, %22, %23, %24, %25, %26, %27, %28, %29, %30, %31}, [%32];" \
        : "=r"((r)[0]),  "=r"((r)[1]),  "=r"((r)[2]),  "=r"((r)[3]), \
          "=r"((r)[4]),  "=r"((r)[5]),  "=r"((r)[6]),  "=r"((r)[7]), \
          "=r"((r)[8]),  "=r"((r)[9]),  "=r"((r)[10]), "=r"((r)[11]), \
          "=r"((r)[12]), "=r"((r)[13]), "=r"((r)[14]), "=r"((r)[15]), \
          "=r"((r)[16]), "=r"((r)[17]), "=r"((r)[18]), "=r"((r)[19]), \
          "=r"((r)[20]), "=r"((r)[21]), "=r"((r)[22]), "=r"((r)[23]), \
          "=r"((r)[24]), "=r"((r)[25]), "=r"((r)[26]), "=r"((r)[27]), \
          "=r"((r)[28]), "=r"((r)[29]), "=r"((r)[30]), "=r"((r)[31]) \
        : "r"(ta))

// SW64 K-major descriptor: layout=4, version=1, SBO=32 (8 rows x 64B = 512B), LBO=1
static constexpr uint64_t DESC_BASE_SW64 =
    (uint64_t(4) << 61) | (uint64_t(1) << 46) | (uint64_t(32) << 32) | (uint64_t(1) << 16);
DEV_INLINE uint64_t make_desc64(uint32_t addr) {
    return DESC_BASE_SW64 | ((uint64_t)(addr >> 4) & 0x3FFF);
}
// idesc kind::f16: fp32 acc, bf16 A, bf16 B, M=128, N=128
#define MMA_IDESC ((1u << 4) | (1u << 7) | (1u << 10) | ((128u / 8u) << 17) | ((128u / 16u) << 24))

DEV_INLINE void mma_bf16_ss(uint32_t d_tmem, uint64_t a_desc, uint64_t b_desc, uint32_t en) {
    asm volatile("{\n\t.reg .pred p;\n\tsetp.ne.u32 p, %4, 0;\n\t"
                 "tcgen05.mma.cta_group::1.kind::f16 [%0], %1, %2, %3, {%5, %5, %5, %5}, p;\n\t}"
                 :: "r"(d_tmem), "l"(a_desc), "l"(b_desc), "r"(MMA_IDESC),
                    "r"(en), "r"(0u)
                 : "memory");
}

// 2D TMA load, multicast to every CTA in mask (same smem offset + complete_tx each)
DEV_INLINE void tma2d_mc(uint32_t dst, const CUtensorMap* map, int x, int y,
                         uint32_t mbar, uint16_t mask) {
    asm volatile("cp.async.bulk.tensor.2d.shared::cluster.global.tile"
                 ".mbarrier::complete_tx::bytes.multicast::cluster "
                 "[%0], [%1, {%2, %3}], [%4], %5;"
                 :: "r"(dst), "l"(map), "r"(x), "r"(y), "r"(mbar), "h"(mask) : "memory");
}
#endif // USE_TC

// ---------------- split helpers ----------------
DEV_INLINE void split1(float v, __nv_bfloat16& h, __nv_bfloat16& l) {
    h = __float2bfloat16(v);
    l = __float2bfloat16(v - __bfloat162float(h));
}

// ---------------- fused prep kernel: split_x + transpose-split_w + probs ----------------
#define PREP_X_BLOCKS 8192     // 8M elems, 4/thread, 256 thr
#define PREP_W_BLOCKS 4096     // 64 x 64 tiles of 32x32
#define PREP_P_BLOCKS 8        // 2048 cols / 256
__global__ void prep_kernel(const float* __restrict__ x, const float* __restrict__ W,
                            const float* __restrict__ E, const float* __restrict__ cb) {
    int b = blockIdx.x;
    int tid = threadIdx.x;
    if (b < PREP_X_BLOCKS) {
        // ---- split x ----
        long i = ((long)b * 256 + tid) * 4;
        float4 v = *(const float4*)(x + i);
        __nv_bfloat16 h0, h1, h2, h3, l0, l1, l2, l3;
        split1(v.x, h0, l0); split1(v.y, h1, l1); split1(v.z, h2, l2); split1(v.w, h3, l3);
        ushort4 hv, lv;
        hv.x = __bfloat16_as_ushort(h0); hv.y = __bfloat16_as_ushort(h1);
        hv.z = __bfloat16_as_ushort(h2); hv.w = __bfloat16_as_ushort(h3);
        lv.x = __bfloat16_as_ushort(l0); lv.y = __bfloat16_as_ushort(l1);
        lv.z = __bfloat16_as_ushort(l2); lv.w = __bfloat16_as_ushort(l3);
        *(ushort4*)((unsigned short*)g_xh + i) = hv;
        *(ushort4*)((unsigned short*)g_xl + i) = lv;
    } else if (b < PREP_X_BLOCKS + PREP_W_BLOCKS) {
        // ---- transpose-split W ----
        __shared__ float t[32][33];
        int wb = b - PREP_X_BLOCKS;
        int j0 = (wb & 63) * 32, k0 = (wb >> 6) * 32;
        int tx = tid & 31, ty = tid >> 5;     // 32 x 8
#pragma unroll
        for (int r = ty; r < 32; r += 8)
            t[r][tx] = W[(long)(k0 + r) * M_DIM + j0 + tx];
        __syncthreads();
#pragma unroll
        for (int r = ty; r < 32; r += 8) {
            float v = t[tx][r];               // = W[k0+tx][j0+r]
            __nv_bfloat16 h, l; split1(v, h, l);
            long o = (long)(j0 + r) * K_DIM + k0 + tx;
            g_wh[o] = h; g_wl[o] = l;
        }
    } else {
        // ---- probs + bias fold: probs[j] = (1/K) * prod cos^2(E[d,j,g]) ----
        int j = (b - PREP_X_BLOCKS - PREP_W_BLOCKS) * 256 + tid;
        if (j < M_DIM) {
            float p = 1.0f;
#pragma unroll
            for (int d = 0; d < 9; d++)
#pragma unroll
                for (int g = 0; g < 3; g++) {
                    float a = E[(long)d * K_DIM * M_DIM + (long)j * M_DIM + g];
                    float c = cosf(a);
                    p *= c * c;
                }
            g_bias[j] = cb[j] + p * (1.0f / (float)K_DIM);
        }
    }
}

#if !USE_TC
// ---------------- hmma tile loader (fallback pass only) ----------------
DEV_INLINE void load_tile_mm(uint32_t smem_base, int stage, int kt, int tileM, int tileN, int tid) {
    uint32_t sb = smem_base + TILE_BASE + stage * MM_STAGE;
#pragma unroll
    for (int i = tid; i < 3072; i += THREADS) {
        if (i < 1024) {
            int hl = i >> 9;
            int t = i & 511; int r = t >> 2, c = t & 3;
            uint32_t dst = sb + hl * MM_A_BYTES + r * MM_ROWB + c * 16;
            long src = (long)(tileM * BM + r) * (K_DIM * 2) + (long)kt * (MM_BK * 2) + c * 16;
            cp16(dst, (const char*)(hl ? (const void*)g_xl : (const void*)g_xh) + src);
        } else {
            int j = i - 1024; int hl = j >> 10;
            int t = j & 1023; int r = t >> 2, c = t & 3;
            uint32_t dst = sb + 2 * MM_A_BYTES + hl * MM_B_BYTES + r * MM_ROWB + c * 16;
            long src = (long)(tileN * BN + r) * (K_DIM * 2) + (long)kt * (MM_BK * 2) + c * 16;
            cp16(dst, (const char*)(hl ? (const void*)g_wl : (const void*)g_wh) + src);
        }
    }
    cp_commit();
}
#endif

// ---------------- main GEMM: warp-specialized TMA + tcgen05, cluster-8 multicast ----------------
__global__ void __launch_bounds__(THREADS, 1) __cluster_dims__(CLUSTER_SZ, 1, 1)
gemm_kernel(float* __restrict__ out,
            const __grid_constant__ CUtensorMap mAh,
            const __grid_constant__ CUtensorMap mAl,
            const __grid_constant__ CUtensorMap mBh,
            const __grid_constant__ CUtensorMap mBl) {
    extern __shared__ char smem[];
    uint32_t smem_base = smem_u32(smem);
    int tid = threadIdx.x;
    int wid = tid >> 5, lid = tid & 31;
    int bid = blockIdx.x;

#if USE_TC
    // ================= tcgen05 + cluster-8 TMA multicast path =================
    // cluster = 4 tileM x 2 tileN. rank bit0 = tileN offset, bits[2:1] = tileM offset.
    uint32_t rank = ctarank();
    int c = bid >> 3;
    int tileM = (c & 7) * 4 + (int)(rank >> 1);   // 0..31
    int tileN = (c >> 3) * 2 + (int)(rank & 1);   // 0..7
    uint16_t amask = (uint16_t)(0x3u << (rank & ~1u));        // same-tileM pair
    uint16_t bmask = (rank & 1) ? (uint16_t)0xAA : (uint16_t)0x55;  // same-tileN quad

    if (wid == 0) TCGEN05_ALLOC(smem_base + SMEM_TMEM_PTR, 256);
    if (tid == 0) {
#pragma unroll
        for (int s = 0; s < NSTAGE; ++s) {
            MBAR_INIT(smem_base + SMEM_FULL(s), 1);   // arrive: producer expect_tx
            MBAR_INIT(smem_base + SMEM_DONE(s), 8);   // arrive: commit-mc from all 8 CTAs
        }
        MBAR_INIT(smem_base + SMEM_FINAL, 1);         // own MMAs only
    }
    __syncthreads();
    uint32_t tmem;
    asm volatile("ld.shared.b32 %0, [%1];" : "=r"(tmem) : "r"(smem_base + SMEM_TMEM_PTR));

    // All 8 CTAs' barriers must be live before any multicast TMA targets them.
    CLUSTER_SYNC();

    uint32_t epred = elect_one();

    if (wid == 1 && epred) {
        // ---- producer: 3 multicast TMAs per stage (A hi|lo slice + 2 B quarter slices) ----
        int arow = tileM * BM;
        int q    = (int)(rank >> 1);                  // B quarter index 0..3
        int brow = tileN * BN + q * 64;
        const CUtensorMap* mapA = (rank & 1) ? &mAl : &mAh;
        uint32_t aoff = (rank & 1) ? STG_AL : STG_A;
        for (int kt = 0; kt < TC_NT; ++kt) {
            int s = kt & (NSTAGE - 1);
            uint32_t fb = smem_base + SMEM_FULL(s);
            if (kt >= NSTAGE)
                mbar_wait(smem_base + SMEM_DONE(s), ((kt - NSTAGE) >> 2) & 1);
            MBAR_EXPECT_TX(fb, STAGE_BYTES);
            uint32_t sa = smem_base + TILE_BASE + s * STAGE_BYTES;
            int kx = kt * TC_BK;
            // A: pair {r, r^1} shares tileM; n==0 loads Ah, n==1 loads Al
            tma2d_mc(sa + aoff, mapA, kx, arow, fb, amask);
            // B: quad {same parity} shares tileN; each loads 64-row quarter of Bh and Bl
            tma2d_mc(sa + STG_BH + q * 4096, &mBh, kx, brow, fb, bmask);
            tma2d_mc(sa + STG_BL + q * 4096, &mBl, kx, brow, fb, bmask);
        }
    } else if (wid == 0 && epred) {
        // ---- consumer: 12 MMAs per stage, commit -> done (all 8 CTAs) ----
        for (int kt = 0; kt < TC_NT; ++kt) {
            int s = kt & (NSTAGE - 1);
            mbar_wait(smem_base + SMEM_FULL(s), (kt >> 2) & 1);

            uint32_t sa  = smem_base + TILE_BASE + s * STAGE_BYTES;
            uint64_t dah = make_desc64(sa + STG_A);
            uint64_t dal = make_desc64(sa + STG_AL);
            uint64_t dbh = make_desc64(sa + STG_BH);
            uint64_t dbl = make_desc64(sa + STG_BL);
#pragma unroll
            for (int ks = 0; ks < 2; ++ks) {               // K=16 per MMA, 2 steps (BK=32)
                uint64_t o = (uint64_t)(ks * 2);           // 32B = 2 desc units
#pragma unroll
                for (int h = 0; h < 2; ++h) {              // two N=128 halves
                    uint64_t bo = o + (uint64_t)h * 512;   // 128 rows * 64B = 8KB = 512 units
                    uint32_t dd = tmem + h * 128;
                    uint32_t acc = (kt > 0) || (ks > 0);
                    mma_bf16_ss(dd, dah + o, dbh + bo, acc);  // hi*hi
                    mma_bf16_ss(dd, dah + o, dbl + bo, 1u);   // hi*lo
                    mma_bf16_ss(dd, dal + o, dbh + bo, 1u);   // lo*hi
                }
            }
            TCGEN05_COMMIT_MC(smem_base + SMEM_DONE(s), 0xFF);
        }
        TCGEN05_COMMIT(smem_base + SMEM_FINAL);        // tracks ALL prior own MMAs
    }

    // Everyone: wait for this CTA's MMAs (count=1, first phase).
    mbar_wait(smem_base + SMEM_FINAL, 0);
    TCGEN05_FENCE_AFTER();

    // Epilogue: 16 warps. warp w -> TMEM lanes (w%4)*32 (its subpartition), cols (w/4)*64
    {
        int rrow  = (wid & 3) * 32 + lid;
        long gm   = (long)tileM * BM + rrow;
        int cbase = (wid >> 2) * 64;
#pragma unroll
        for (int cc = 0; cc < 2; ++cc) {
            uint32_t d[32];
            TCGEN05_LD_X32(d, tmem + cbase + cc * 32);
            TCGEN05_WAIT_LD();
            int gc = tileN * BN + cbase + cc * 32;
            const float4* bp = (const float4*)(g_bias + gc);
            float4* op = (float4*)(out + gm * M_DIM + gc);
#pragma unroll
            for (int q2 = 0; q2 < 8; ++q2) {
                float4 b = bp[q2];
                float4 o;
                o.x = tanhf(__uint_as_float(d[q2 * 4 + 0]) + b.x);
                o.y = tanhf(__uint_as_float(d[q2 * 4 + 1]) + b.y);
                o.z = tanhf(__uint_as_float(d[q2 * 4 + 2]) + b.z);
                o.w = tanhf(__uint_as_float(d[q2 * 4 + 3]) + b.w);
                op[q2] = o;
            }
        }
        TCGEN05_FENCE_BEFORE();
    }

    __syncthreads();
    if (tid == 0) {
#pragma unroll
        for (int s = 0; s < NSTAGE; ++s) {
            MBAR_INVAL(smem_base + SMEM_FULL(s));
            MBAR_INVAL(smem_base + SMEM_DONE(s));
        }
        MBAR_INVAL(smem_base + SMEM_FINAL);
    }
    __syncthreads();
    if (wid == 0) TCGEN05_DEALLOC(tmem, 256);
    // No CTA exits while a peer's multicast targeting this CTA could be in flight.
    CLUSTER_SYNC();

#else
    // ================= HMMA fallback (base-PTX legal; never runs on GB300) =================
    int c = bid >> 3;
    uint32_t rank = (uint32_t)(bid & 7);
    int tileM = (c & 7) * 4 + (int)(rank >> 1);
    int tileN = (c >> 3) * 2 + (int)(rank & 1);
    int wr = wid & 3;
    int wc = wid >> 2;

    float acc[2][8][4];
#pragma unroll
    for (int mt = 0; mt < 2; ++mt)
#pragma unroll
        for (int nt = 0; nt < 8; ++nt)
#pragma unroll
            for (int q = 0; q < 4; ++q) acc[mt][nt][q] = 0.0f;

    load_tile_mm(smem_base, 0, 0, tileM, tileN, tid);
    load_tile_mm(smem_base, 1, 1, tileM, tileN, tid);
    load_tile_mm(smem_base, 2, 2, tileM, tileN, tid);

    const int lrow = lid & 15;
    const int lk16b = (lid >> 4) * 16;

    for (int kt = 0; kt < MM_NT; ++kt) {
        asm volatile("cp.async.wait_group 2;" ::: "memory");
        __syncthreads();

        int s = kt % MM_STAGES;
        uint32_t sb  = smem_base + TILE_BASE + s * MM_STAGE;
        uint32_t sAh = sb;
        uint32_t sAl = sb + MM_A_BYTES;
        uint32_t sBh = sb + 2 * MM_A_BYTES;
        uint32_t sBl = sb + 2 * MM_A_BYTES + MM_B_BYTES;

#pragma unroll
        for (int k16 = 0; k16 < 2; ++k16) {
            uint32_t koff = k16 * 32 + lk16b;
            uint32_t aoff = (uint32_t)(wr * 32 + lrow) * MM_ROWB + koff;
            uint32_t boff = (uint32_t)(wc * 64 + lrow) * MM_ROWB + koff;

            uint32_t ah[2][4], bh[4][4];
            ldsm4(ah[0], sAh + aoff);
            ldsm4(ah[1], sAh + aoff + 16 * MM_ROWB);
#pragma unroll
            for (int g = 0; g < 4; ++g) ldsm4(bh[g], sBh + boff + g * 16 * MM_ROWB);

#pragma unroll
            for (int mt = 0; mt < 2; ++mt)
#pragma unroll
                for (int nt = 0; nt < 8; ++nt)
                    mma16816(acc[mt][nt], ah[mt], bh[nt >> 1][nt & 1], bh[nt >> 1][(nt & 1) + 2]);

            uint32_t al[2][4];
            ldsm4(al[0], sAl + aoff);
            ldsm4(al[1], sAl + aoff + 16 * MM_ROWB);
#pragma unroll
            for (int mt = 0; mt < 2; ++mt)
#pragma unroll
                for (int nt = 0; nt < 8; ++nt)
                    mma16816(acc[mt][nt], al[mt], bh[nt >> 1][nt & 1], bh[nt >> 1][(nt & 1) + 2]);

            uint32_t bl[4][4];
#pragma unroll
            for (int g = 0; g < 4; ++g) ldsm4(bl[g], sBl + boff + g * 16 * MM_ROWB);
#pragma unroll
            for (int mt = 0; mt < 2; ++mt)
#pragma unroll
                for (int nt = 0; nt < 8; ++nt)
                    mma16816(acc[mt][nt], ah[mt], bl[nt >> 1][nt & 1], bl[nt >> 1][(nt & 1) + 2]);
        }

        __syncthreads();
        if (kt + MM_STAGES < MM_NT)
            load_tile_mm(smem_base, s, kt + MM_STAGES, tileM, tileN, tid);
    }

    {
        int r0 = tileM * BM + wr * 32 + (lid >> 2);
        int c0 = tileN * BN + wc * 64 + (lid & 3) * 2;
#pragma unroll
        for (int mt = 0; mt < 2; ++mt) {
#pragma unroll
            for (int nt = 0; nt < 8; ++nt) {
                int row = r0 + mt * 16;
                int col = c0 + nt * 8;
                float2 bv = *(const float2*)(g_bias + col);
                float2 o0, o1;
                o0.x = tanhf(acc[mt][nt][0] + bv.x);
                o0.y = tanhf(acc[mt][nt][1] + bv.y);
                o1.x = tanhf(acc[mt][nt][2] + bv.x);
                o1.y = tanhf(acc[mt][nt][3] + bv.y);
                *(float2*)(out + (long)row * M_DIM + col) = o0;
                *(float2*)(out + (long)(row + 8) * M_DIM + col) = o1;
            }
        }
    }
#endif
}

// ---------------- host: tensormap creation via driver entry point ----------------
typedef CUresult (*EncodeTiledFn)(
    CUtensorMap*, CUtensorMapDataType, cuuint32_t, void*,
    const cuuint64_t*, const cuuint64_t*, const cuuint32_t*, const cuuint32_t*,
    CUtensorMapInterleave, CUtensorMapSwizzle, CUtensorMapL2promotion, CUtensorMapFloatOOBfill);

static void make_map(EncodeTiledFn enc, CUtensorMap* m, void* base,
                     unsigned long long rows, unsigned box_rows) {
    cuuint64_t dims[2]    = {(cuuint64_t)K_DIM, (cuuint64_t)rows};
    cuuint64_t strides[1] = {(cuuint64_t)K_DIM * 2};           // bytes between rows
    cuuint32_t box[2]     = {32, box_rows};                    // 64B x box_rows (SW64)
    cuuint32_t es[2]      = {1, 1};
    enc(m, CU_TENSOR_MAP_DATA_TYPE_BFLOAT16, 2, base, dims, strides, box, es,
        CU_TENSOR_MAP_INTERLEAVE_NONE, CU_TENSOR_MAP_SWIZZLE_64B,
        CU_TENSOR_MAP_L2_PROMOTION_L2_128B, CU_TENSOR_MAP_FLOAT_OOB_FILL_NONE);
}

extern "C" void kernel_launch(void* const* d_in, const int* in_sizes, int n_in,
                              void* d_out, int out_size) {
    const float* x  = (const float*)d_in[0];
    const float* E  = (const float*)d_in[1];
    // d_in[2] = eternal_biases: unused by the reference as well
    const float* W  = (const float*)d_in[3];
    const float* cb = (const float*)d_in[4];
    float* out = (float*)d_out;

    // tensormaps (host-side; recreated per call — deterministic, no device work)
    EncodeTiledFn enc = nullptr;
    cudaDriverEntryPointQueryResult qr;
    cudaGetDriverEntryPointByVersion("cuTensorMapEncodeTiled", (void**)&enc, 12000,
                                     cudaEnableDefault, &qr);
    void *pxh, *pxl, *pwh, *pwl;
    cudaGetSymbolAddress(&pxh, g_xh);
    cudaGetSymbolAddress(&pxl, g_xl);
    cudaGetSymbolAddress(&pwh, g_wh);
    cudaGetSymbolAddress(&pwl, g_wl);
    CUtensorMap mAh, mAl, mBh, mBl;
    make_map(enc, &mAh, pxh, B_DIM, 128);   // A slices: full 128-row tile
    make_map(enc, &mAl, pxl, B_DIM, 128);
    make_map(enc, &mBh, pwh, M_DIM, 64);    // B slices: 64-row quarters
    make_map(enc, &mBl, pwl, M_DIM, 64);

    cudaFuncSetAttribute(gemm_kernel, cudaFuncAttributeMaxDynamicSharedMemorySize, SMEM_TOTAL);

    prep_kernel<<<PREP_X_BLOCKS + PREP_W_BLOCKS + PREP_P_BLOCKS, 256>>>(x, W, E, cb);
    gemm_kernel<<<(B_DIM / BM) * (M_DIM / BN), THREADS, SMEM_TOTAL>>>(out, mAh, mAl, mBh, mBl);
}

// round 13
// speedup vs baseline: 1.3427x; 1.3427x over previous
#include <cuda_runtime.h>
#include <cuda.h>
#include <cuda_bf16.h>
#include <cstdint>
#include <math.h>

#define DEV_INLINE __device__ __forceinline__

// Does this compilation pass target sm_103a (arch-specific features available)?
#ifdef __CUDA_ARCH_FEAT_SM103_ALL
#define USE_TC 1
#else
#define USE_TC 0
#endif

// ---------------- problem constants ----------------
#define B_DIM 4096          // batch rows (GEMM M)
#define K_DIM 2048          // inner dim  (GEMM K)
#define M_DIM 2048          // out cols   (GEMM N)

#define THREADS 512
#define CLUSTER_SZ 2

// ---- tcgen05 cg2 path: pair computes 256(M) x 256(N); per CTA 128 A-rows + 128 B-rows ----
#define PAIR_M 256
#define PAIR_N 256
#define TC_BK  32
#define TC_NT  (K_DIM / TC_BK)                 // 64
#define NSTAGE 4
// per-CTA stage: Ah(8K) Al(8K) Bh_half(8K) Bl_half(8K) = 32KB
#define STG_A   0
#define STG_AL  8192
#define STG_BH  16384
#define STG_BL  24576
#define STAGE_BYTES 32768
#define SMEM_TMEM_PTR 0
#define SMEM_FULL(s)  (8 + (s) * 8)            // leader-side tx barriers (armed on rank0)
#define SMEM_DONE(s)  (40 + (s) * 8)           // commit-mc arrival, both CTAs
#define SMEM_FINAL    72
#define TILE_BASE     1024

// ---- hmma fallback smem (compile-legality for the compute_103 PTX pass) ----
#define BM 128
#define BN 256
#define MM_BK         32
#define MM_NT         (K_DIM / MM_BK)              // 64
#define MM_ROWB       80                           // 64B row + 16B pad
#define MM_A_BYTES    (BM * MM_ROWB)               // 10240
#define MM_B_BYTES    (BN * MM_ROWB)               // 20480
#define MM_STAGE      (2 * MM_A_BYTES + 2 * MM_B_BYTES)  // 61440
#define MM_STAGES     3
#define SMEM_TOTAL    (TILE_BASE + MM_STAGES * MM_STAGE) // 185344 (covers TC path's 132KB too)

// ---------------- device scratch (allocation-free rule: __device__ globals) ----------------
__device__ __align__(16) __nv_bfloat16 g_xh[(long)B_DIM * K_DIM];
__device__ __align__(16) __nv_bfloat16 g_xl[(long)B_DIM * K_DIM];
__device__ __align__(16) __nv_bfloat16 g_wh[(long)M_DIM * K_DIM];   // [j][k] (transposed W)
__device__ __align__(16) __nv_bfloat16 g_wl[(long)M_DIM * K_DIM];
__device__ float g_bias[M_DIM];                                     // classical_bias + probs

// ---------------- PTX helpers (base-arch legal) ----------------
DEV_INLINE uint32_t smem_u32(const void* p) {
    uint32_t a;
    asm("{ .reg .u64 t; cvta.to.shared.u64 t, %1; cvt.u32.u64 %0, t; }" : "=r"(a) : "l"(p));
    return a;
}

DEV_INLINE void cp16(uint32_t dst, const void* src) {
    asm volatile("cp.async.cg.shared.global [%0], [%1], 16;" :: "r"(dst), "l"(src) : "memory");
}
DEV_INLINE void cp_commit() { asm volatile("cp.async.commit_group;" ::: "memory"); }

DEV_INLINE void ldsm4(uint32_t* r, uint32_t addr) {
    asm volatile("ldmatrix.sync.aligned.m8n8.x4.shared.b16 {%0,%1,%2,%3}, [%4];"
                 : "=r"(r[0]), "=r"(r[1]), "=r"(r[2]), "=r"(r[3]) : "r"(addr));
}
DEV_INLINE void mma16816(float* c, const uint32_t* a, uint32_t b0, uint32_t b1) {
    asm volatile("mma.sync.aligned.m16n8k16.row.col.f32.bf16.bf16.f32 "
                 "{%0,%1,%2,%3}, {%4,%5,%6,%7}, {%8,%9}, {%0,%1,%2,%3};"
                 : "+f"(c[0]), "+f"(c[1]), "+f"(c[2]), "+f"(c[3])
                 : "r"(a[0]), "r"(a[1]), "r"(a[2]), "r"(a[3]), "r"(b0), "r"(b1));
}

#if USE_TC
// ---------------- tcgen05 / TMA helpers (only in the sm_103a pass) ----------------
DEV_INLINE uint32_t elect_one() {
    uint32_t pred;
    asm volatile("{\n\t.reg .pred p;\n\telect.sync _|p, 0xFFFFFFFF;\n\t"
                 "selp.b32 %0, 1, 0, p;\n\t}" : "=r"(pred));
    return pred;
}
DEV_INLINE uint32_t ctarank() {
    uint32_t r;
    asm("mov.u32 %0, %%cluster_ctarank;" : "=r"(r));
    return r;
}
#define MBAR_INIT(addr, cnt) \
    asm volatile("mbarrier.init.shared.b64 [%0], %1;" :: "r"(addr), "r"(cnt) : "memory")
#define MBAR_INVAL(addr) \
    asm volatile("mbarrier.inval.shared.b64 [%0];" :: "r"(addr) : "memory")
#define MBAR_EXPECT_TX(addr, tx) \
    asm volatile("mbarrier.arrive.expect_tx.shared.b64 _, [%0], %1;" \
                 :: "r"(addr), "r"((uint32_t)(tx)) : "memory")
#define CLUSTER_SYNC() do { \
    asm volatile("barrier.cluster.arrive.aligned;" ::: "memory"); \
    asm volatile("barrier.cluster.wait.aligned;" ::: "memory"); \
} while (0)

DEV_INLINE void mbar_wait(uint32_t mbar, uint32_t parity) {
    uint32_t done;
    asm volatile("{\n\t.reg .pred p;\n\t"
                 "mbarrier.try_wait.parity.acquire.cta.shared::cta.b64 p, [%1], %2;\n\t"
                 "selp.b32 %0, 1, 0, p;\n\t}"
                 : "=r"(done) : "r"(mbar), "r"(parity) : "memory");
    if (!done) {
        asm volatile("{\n\t.reg .pred P1;\n\t"
                     "W_%=:\n\t"
                     "mbarrier.try_wait.parity.acquire.cta.shared::cta.b64 P1, [%0], %1, 0x989680;\n\t"
                     "@P1 bra.uni D_%=;\n\t"
                     "bra.uni W_%=;\n\t"
                     "D_%=:\n\t}"
                     :: "r"(mbar), "r"(parity) : "memory");
    }
}

#define TCGEN05_ALLOC_CG2(sm_addr, nc) \
    asm volatile("tcgen05.alloc.cta_group::2.sync.aligned.shared::cta.b32 [%0], %1;" \
                 :: "r"((uint32_t)(sm_addr)), "r"((uint32_t)(nc)) : "memory")
#define TCGEN05_DEALLOC_CG2(tmem, nc) \
    asm volatile("tcgen05.dealloc.cta_group::2.sync.aligned.b32 %0, %1;" :: "r"(tmem), "r"(nc))
#define TCGEN05_RELINQUISH_CG2() \
    asm volatile("tcgen05.relinquish_alloc_permit.cta_group::2.sync.aligned;")
#define TCGEN05_COMMIT_MC_CG2(mbar, mask) \
    asm volatile("tcgen05.commit.cta_group::2.mbarrier::arrive::one.shared::cluster.multicast::cluster.b64 [%0], %1;" \
                 :: "r"((uint32_t)(mbar)), "h"((uint16_t)(mask)) : "memory")
#define TCGEN05_FENCE_AFTER()  asm volatile("tcgen05.fence::after_thread_sync;" ::: "memory")
#define TCGEN05_FENCE_BEFORE() asm volatile("tcgen05.fence::before_thread_sync;" ::: "memory")
#define TCGEN05_WAIT_LD()      asm volatile("tcgen05.wait::ld.sync.aligned;" ::: "memory")

#define TCGEN05_LD_X32(r, ta) \
    asm volatile("tcgen05.ld.sync.aligned.32x32b.x32.b32 " \
        "{%0, %1, %2, %3, %4, %5, %6, %7, %8, %9, %10, %11, %12, %13, %14, %15, " \
        " %16, %17, %18, %19, %20, %21, %22, %23, %24, %25, %26, %27, %28, %29, %30, %31}, [%32];" \
        : "=r"((r)[0]),  "=r"((r)[1]),  "=r"((r)[2]),  "=r"((r)[3]), \
          "=r"((r)[4]),  "=r"((r)[5]),  "=r"((r)[6]),  "=r"((r)[7]), \
          "=r"((r)[8]),  "=r"((r)[9]),  "=r"((r)[10]), "=r"((r)[11]), \
          "=r"((r)[12]), "=r"((r)[13]), "=r"((r)[14]), "=r"((r)[15]), \
          "=r"((r)[16]), "=r"((r)[17]), "=r"((r)[18]), "=r"((r)[19]), \
          "=r"((r)[20]), "=r"((r)[21]), "=r"((r)[22]), "=r"((r)[23]), \
          "=r"((r)[24]), "=r"((r)[25]), "=r"((r)[26]), "=r"((r)[27]), \
          "=r"((r)[28]), "=r"((r)[29]), "=r"((r)[30]), "=r"((r)[31]) \
        : "r"(ta))

// SW64 K-major descriptor: layout=4, version=1, SBO=32 (8 rows x 64B = 512B), LBO=1
static constexpr uint64_t DESC_BASE_SW64 =
    (uint64_t(4) << 61) | (uint64_t(1) << 46) | (uint64_t(32) << 32) | (uint64_t(1) << 16);
DEV_INLINE uint64_t make_desc64(uint32_t addr) {
    return DESC_BASE_SW64 | ((uint64_t)(addr >> 4) & 0x3FFF);
}
// idesc kind::f16 cg2: fp32 acc, bf16 A, bf16 B, M=256 (pair), N=256
#define MMA_IDESC_CG2 ((1u << 4) | (1u << 7) | (1u << 10) | ((PAIR_N / 8u) << 17) | ((PAIR_M / 16u) << 24))

DEV_INLINE void mma_bf16_ss_cg2(uint32_t d_tmem, uint64_t a_desc, uint64_t b_desc, uint32_t en) {
    asm volatile("{\n\t.reg .pred p;\n\tsetp.ne.u32 p, %4, 0;\n\t"
                 "tcgen05.mma.cta_group::2.kind::f16 [%0], %1, %2, %3, "
                 "{%5, %5, %5, %5, %5, %5, %5, %5}, p;\n\t}"
                 :: "r"(d_tmem), "l"(a_desc), "l"(b_desc), "r"(MMA_IDESC_CG2),
                    "r"(en), "r"(0u)
                 : "memory");
}

// 2D TMA load, cta_group::2: both CTAs issue; complete_tx targets the LEADER's barrier
// (clear Sm100MmaPeerBitMask bit 24 of the local barrier address).
DEV_INLINE void tma2d_cg2(uint32_t dst, const CUtensorMap* map, int x, int y, uint32_t mbar) {
    asm volatile("{\n\t.reg .b32 lb;\n\t"
                 "and.b32 lb, %4, 0xFEFFFFFF;\n\t"
                 "cp.async.bulk.tensor.2d.cta_group::2.shared::cluster.global.tile"
                 ".mbarrier::complete_tx::bytes [%0], [%1, {%2, %3}], [lb];\n\t}"
                 :: "r"(dst), "l"(map), "r"(x), "r"(y), "r"(mbar) : "memory");
}
#endif // USE_TC

// ---------------- split helpers ----------------
DEV_INLINE void split1(float v, __nv_bfloat16& h, __nv_bfloat16& l) {
    h = __float2bfloat16(v);
    l = __float2bfloat16(v - __bfloat162float(h));
}

// ---------------- fused prep kernel: split_x + transpose-split_w + probs ----------------
#define PREP_X_BLOCKS 8192     // 8M elems, 4/thread, 256 thr
#define PREP_W_BLOCKS 4096     // 64 x 64 tiles of 32x32
#define PREP_P_BLOCKS 8        // 2048 cols / 256
__global__ void prep_kernel(const float* __restrict__ x, const float* __restrict__ W,
                            const float* __restrict__ E, const float* __restrict__ cb) {
    int b = blockIdx.x;
    int tid = threadIdx.x;
    if (b < PREP_X_BLOCKS) {
        // ---- split x ----
        long i = ((long)b * 256 + tid) * 4;
        float4 v = *(const float4*)(x + i);
        __nv_bfloat16 h0, h1, h2, h3, l0, l1, l2, l3;
        split1(v.x, h0, l0); split1(v.y, h1, l1); split1(v.z, h2, l2); split1(v.w, h3, l3);
        ushort4 hv, lv;
        hv.x = __bfloat16_as_ushort(h0); hv.y = __bfloat16_as_ushort(h1);
        hv.z = __bfloat16_as_ushort(h2); hv.w = __bfloat16_as_ushort(h3);
        lv.x = __bfloat16_as_ushort(l0); lv.y = __bfloat16_as_ushort(l1);
        lv.z = __bfloat16_as_ushort(l2); lv.w = __bfloat16_as_ushort(l3);
        *(ushort4*)((unsigned short*)g_xh + i) = hv;
        *(ushort4*)((unsigned short*)g_xl + i) = lv;
    } else if (b < PREP_X_BLOCKS + PREP_W_BLOCKS) {
        // ---- transpose-split W ----
        __shared__ float t[32][33];
        int wb = b - PREP_X_BLOCKS;
        int j0 = (wb & 63) * 32, k0 = (wb >> 6) * 32;
        int tx = tid & 31, ty = tid >> 5;     // 32 x 8
#pragma unroll
        for (int r = ty; r < 32; r += 8)
            t[r][tx] = W[(long)(k0 + r) * M_DIM + j0 + tx];
        __syncthreads();
#pragma unroll
        for (int r = ty; r < 32; r += 8) {
            float v = t[tx][r];               // = W[k0+tx][j0+r]
            __nv_bfloat16 h, l; split1(v, h, l);
            long o = (long)(j0 + r) * K_DIM + k0 + tx;
            g_wh[o] = h; g_wl[o] = l;
        }
    } else {
        // ---- probs + bias fold: probs[j] = (1/K) * prod cos^2(E[d,j,g]) ----
        int j = (b - PREP_X_BLOCKS - PREP_W_BLOCKS) * 256 + tid;
        if (j < M_DIM) {
            float p = 1.0f;
#pragma unroll
            for (int d = 0; d < 9; d++)
#pragma unroll
                for (int g = 0; g < 3; g++) {
                    float a = E[(long)d * K_DIM * M_DIM + (long)j * M_DIM + g];
                    float c = cosf(a);
                    p *= c * c;
                }
            g_bias[j] = cb[j] + p * (1.0f / (float)K_DIM);
        }
    }
}

#if !USE_TC
// ---------------- hmma tile loader (fallback pass only) ----------------
DEV_INLINE void load_tile_mm(uint32_t smem_base, int stage, int kt, int tileM, int tileN, int tid) {
    uint32_t sb = smem_base + TILE_BASE + stage * MM_STAGE;
#pragma unroll
    for (int i = tid; i < 3072; i += THREADS) {
        if (i < 1024) {
            int hl = i >> 9;
            int t = i & 511; int r = t >> 2, c = t & 3;
            uint32_t dst = sb + hl * MM_A_BYTES + r * MM_ROWB + c * 16;
            long src = (long)(tileM * BM + r) * (K_DIM * 2) + (long)kt * (MM_BK * 2) + c * 16;
            cp16(dst, (const char*)(hl ? (const void*)g_xl : (const void*)g_xh) + src);
        } else {
            int j = i - 1024; int hl = j >> 10;
            int t = j & 1023; int r = t >> 2, c = t & 3;
            uint32_t dst = sb + 2 * MM_A_BYTES + hl * MM_B_BYTES + r * MM_ROWB + c * 16;
            long src = (long)(tileN * BN + r) * (K_DIM * 2) + (long)kt * (MM_BK * 2) + c * 16;
            cp16(dst, (const char*)(hl ? (const void*)g_wl : (const void*)g_wh) + src);
        }
    }
    cp_commit();
}
#endif

// ---------------- main GEMM: warp-specialized TMA + cg2 tcgen05, 4-stage ring ----------------
__global__ void __launch_bounds__(THREADS, 1) __cluster_dims__(CLUSTER_SZ, 1, 1)
gemm_kernel(float* __restrict__ out,
            const __grid_constant__ CUtensorMap mAh,
            const __grid_constant__ CUtensorMap mAl,
            const __grid_constant__ CUtensorMap mBh,
            const __grid_constant__ CUtensorMap mBl) {
    extern __shared__ char smem[];
    uint32_t smem_base = smem_u32(smem);
    int tid = threadIdx.x;
    int wid = tid >> 5, lid = tid & 31;
    int bid = blockIdx.x;

#if USE_TC
    // ================= cg2 tcgen05 path: pair computes 256x256 =================
    uint32_t rank = ctarank();
    int c = bid >> 1;
    int tileM = c & 15;          // 16 tileM values; consecutive pairs share tileN band
    int tileN = c >> 4;          // 0..7

    if (wid == 0) TCGEN05_ALLOC_CG2(smem_base + SMEM_TMEM_PTR, 256);
    if (tid == 0) {
#pragma unroll
        for (int s = 0; s < NSTAGE; ++s) {
            MBAR_INIT(smem_base + SMEM_FULL(s), 1);   // rank0: armed by producer expect_tx
            MBAR_INIT(smem_base + SMEM_DONE(s), 1);   // commit-mc arrival (one per CTA)
        }
        MBAR_INIT(smem_base + SMEM_FINAL, 1);
    }
    __syncthreads();
    uint32_t tmem;
    asm volatile("ld.shared.b32 %0, [%1];" : "=r"(tmem) : "r"(smem_base + SMEM_TMEM_PTR));

    // Both CTAs' barriers must be live before any cg2 TMA/commit targets them.
    CLUSTER_SYNC();

    uint32_t epred = elect_one();

    if (wid == 1 && epred) {
        // ---- producer (both CTAs): 4 cg2 TMAs per stage -> leader's FULL(s) ----
        int arow = tileM * PAIR_M + (int)rank * 128;   // this CTA's 128 A rows
        int brow = tileN * PAIR_N + (int)rank * 128;   // this CTA's 128 B rows (N-split)
        for (int kt = 0; kt < TC_NT; ++kt) {
            int s = kt & (NSTAGE - 1);
            if (kt >= NSTAGE)
                mbar_wait(smem_base + SMEM_DONE(s), ((kt - NSTAGE) >> 2) & 1);
            if (rank == 0)
                MBAR_EXPECT_TX(smem_base + SMEM_FULL(s), 2 * STAGE_BYTES);  // both CTAs' loads
            uint32_t sa = smem_base + TILE_BASE + s * STAGE_BYTES;
            int kx = kt * TC_BK;
            tma2d_cg2(sa + STG_A,  &mAh, kx, arow, smem_base + SMEM_FULL(s));
            tma2d_cg2(sa + STG_AL, &mAl, kx, arow, smem_base + SMEM_FULL(s));
            tma2d_cg2(sa + STG_BH, &mBh, kx, brow, smem_base + SMEM_FULL(s));
            tma2d_cg2(sa + STG_BL, &mBl, kx, brow, smem_base + SMEM_FULL(s));
        }
    } else if (rank == 0 && wid == 0 && epred) {
        // ---- consumer (leader only): 6 cg2 MMAs per stage, commit-mc -> DONE both ----
        for (int kt = 0; kt < TC_NT; ++kt) {
            int s = kt & (NSTAGE - 1);
            mbar_wait(smem_base + SMEM_FULL(s), (kt >> 2) & 1);

            uint32_t sa  = smem_base + TILE_BASE + s * STAGE_BYTES;
            uint64_t dah = make_desc64(sa + STG_A);
            uint64_t dal = make_desc64(sa + STG_AL);
            uint64_t dbh = make_desc64(sa + STG_BH);
            uint64_t dbl = make_desc64(sa + STG_BL);
#pragma unroll
            for (int ks = 0; ks < 2; ++ks) {               // K=16 per MMA, 2 steps (BK=32)
                uint64_t o = (uint64_t)(ks * 2);           // 32B = 2 desc units
                uint32_t acc = (kt > 0) || (ks > 0);
                mma_bf16_ss_cg2(tmem, dah + o, dbh + o, acc);  // hi*hi
                mma_bf16_ss_cg2(tmem, dah + o, dbl + o, 1u);   // hi*lo
                mma_bf16_ss_cg2(tmem, dal + o, dbh + o, 1u);   // lo*hi
            }
            TCGEN05_COMMIT_MC_CG2(smem_base + SMEM_DONE(s), 3);
        }
        TCGEN05_COMMIT_MC_CG2(smem_base + SMEM_FINAL, 3);  // tracks ALL prior MMAs, both CTAs
    }

    // Everyone: wait for all pair MMAs (count=1, first phase).
    mbar_wait(smem_base + SMEM_FINAL, 0);
    TCGEN05_FENCE_AFTER();

    // Epilogue: 16 warps; this CTA's TMEM = its 128 rows x 256 cols.
    // warp w -> lanes (w%4)*32 (its subpartition), col block (w/4)*64.
    {
        int rrow  = (wid & 3) * 32 + lid;
        long gm   = (long)tileM * PAIR_M + (long)rank * 128 + rrow;
        int cbase = (wid >> 2) * 64;
#pragma unroll
        for (int cc = 0; cc < 2; ++cc) {
            uint32_t d[32];
            TCGEN05_LD_X32(d, tmem + cbase + cc * 32);
            TCGEN05_WAIT_LD();
            int gc = tileN * PAIR_N + cbase + cc * 32;
            const float4* bp = (const float4*)(g_bias + gc);
            float4* op = (float4*)(out + gm * M_DIM + gc);
#pragma unroll
            for (int q2 = 0; q2 < 8; ++q2) {
                float4 b = bp[q2];
                float4 o;
                o.x = tanhf(__uint_as_float(d[q2 * 4 + 0]) + b.x);
                o.y = tanhf(__uint_as_float(d[q2 * 4 + 1]) + b.y);
                o.z = tanhf(__uint_as_float(d[q2 * 4 + 2]) + b.z);
                o.w = tanhf(__uint_as_float(d[q2 * 4 + 3]) + b.w);
                op[q2] = o;
            }
        }
        TCGEN05_FENCE_BEFORE();
    }

    __syncthreads();
    if (tid == 0) {
#pragma unroll
        for (int s = 0; s < NSTAGE; ++s) {
            MBAR_INVAL(smem_base + SMEM_FULL(s));
            MBAR_INVAL(smem_base + SMEM_DONE(s));
        }
        MBAR_INVAL(smem_base + SMEM_FINAL);
    }
    __syncthreads();
    if (wid == 0) {
        TCGEN05_RELINQUISH_CG2();
        TCGEN05_DEALLOC_CG2(tmem, 256);
    }
    // No CTA exits while the peer's cg2 traffic targeting this CTA could be in flight.
    CLUSTER_SYNC();

#else
    // ================= HMMA fallback (base-PTX legal; never runs on GB300) =================
    int tileM = bid & 31;
    int tileN = bid >> 5;
    int wr = wid & 3;
    int wc = wid >> 2;

    float acc[2][8][4];
#pragma unroll
    for (int mt = 0; mt < 2; ++mt)
#pragma unroll
        for (int nt = 0; nt < 8; ++nt)
#pragma unroll
            for (int q = 0; q < 4; ++q) acc[mt][nt][q] = 0.0f;

    load_tile_mm(smem_base, 0, 0, tileM, tileN, tid);
    load_tile_mm(smem_base, 1, 1, tileM, tileN, tid);
    load_tile_mm(smem_base, 2, 2, tileM, tileN, tid);

    const int lrow = lid & 15;
    const int lk16b = (lid >> 4) * 16;

    for (int kt = 0; kt < MM_NT; ++kt) {
        asm volatile("cp.async.wait_group 2;" ::: "memory");
        __syncthreads();

        int s = kt % MM_STAGES;
        uint32_t sb  = smem_base + TILE_BASE + s * MM_STAGE;
        uint32_t sAh = sb;
        uint32_t sAl = sb + MM_A_BYTES;
        uint32_t sBh = sb + 2 * MM_A_BYTES;
        uint32_t sBl = sb + 2 * MM_A_BYTES + MM_B_BYTES;

#pragma unroll
        for (int k16 = 0; k16 < 2; ++k16) {
            uint32_t koff = k16 * 32 + lk16b;
            uint32_t aoff = (uint32_t)(wr * 32 + lrow) * MM_ROWB + koff;
            uint32_t boff = (uint32_t)(wc * 64 + lrow) * MM_ROWB + koff;

            uint32_t ah[2][4], bh[4][4];
            ldsm4(ah[0], sAh + aoff);
            ldsm4(ah[1], sAh + aoff + 16 * MM_ROWB);
#pragma unroll
            for (int g = 0; g < 4; ++g) ldsm4(bh[g], sBh + boff + g * 16 * MM_ROWB);

#pragma unroll
            for (int mt = 0; mt < 2; ++mt)
#pragma unroll
                for (int nt = 0; nt < 8; ++nt)
                    mma16816(acc[mt][nt], ah[mt], bh[nt >> 1][nt & 1], bh[nt >> 1][(nt & 1) + 2]);

            uint32_t al[2][4];
            ldsm4(al[0], sAl + aoff);
            ldsm4(al[1], sAl + aoff + 16 * MM_ROWB);
#pragma unroll
            for (int mt = 0; mt < 2; ++mt)
#pragma unroll
                for (int nt = 0; nt < 8; ++nt)
                    mma16816(acc[mt][nt], al[mt], bh[nt >> 1][nt & 1], bh[nt >> 1][(nt & 1) + 2]);

            uint32_t bl[4][4];
#pragma unroll
            for (int g = 0; g < 4; ++g) ldsm4(bl[g], sBl + boff + g * 16 * MM_ROWB);
#pragma unroll
            for (int mt = 0; mt < 2; ++mt)
#pragma unroll
                for (int nt = 0; nt < 8; ++nt)
                    mma16816(acc[mt][nt], ah[mt], bl[nt >> 1][nt & 1], bl[nt >> 1][(nt & 1) + 2]);
        }

        __syncthreads();
        if (kt + MM_STAGES < MM_NT)
            load_tile_mm(smem_base, s, kt + MM_STAGES, tileM, tileN, tid);
    }

    {
        int r0 = tileM * BM + wr * 32 + (lid >> 2);
        int c0 = tileN * BN + wc * 64 + (lid & 3) * 2;
#pragma unroll
        for (int mt = 0; mt < 2; ++mt) {
#pragma unroll
            for (int nt = 0; nt < 8; ++nt) {
                int row = r0 + mt * 16;
                int col = c0 + nt * 8;
                float2 bv = *(const float2*)(g_bias + col);
                float2 o0, o1;
                o0.x = tanhf(acc[mt][nt][0] + bv.x);
                o0.y = tanhf(acc[mt][nt][1] + bv.y);
                o1.x = tanhf(acc[mt][nt][2] + bv.x);
                o1.y = tanhf(acc[mt][nt][3] + bv.y);
                *(float2*)(out + (long)row * M_DIM + col) = o0;
                *(float2*)(out + (long)(row + 8) * M_DIM + col) = o1;
            }
        }
    }
#endif
}

// ---------------- host: tensormap creation via driver entry point ----------------
typedef CUresult (*EncodeTiledFn)(
    CUtensorMap*, CUtensorMapDataType, cuuint32_t, void*,
    const cuuint64_t*, const cuuint64_t*, const cuuint32_t*, const cuuint32_t*,
    CUtensorMapInterleave, CUtensorMapSwizzle, CUtensorMapL2promotion, CUtensorMapFloatOOBfill);

static void make_map(EncodeTiledFn enc, CUtensorMap* m, void* base,
                     unsigned long long rows, unsigned box_rows) {
    cuuint64_t dims[2]    = {(cuuint64_t)K_DIM, (cuuint64_t)rows};
    cuuint64_t strides[1] = {(cuuint64_t)K_DIM * 2};           // bytes between rows
    cuuint32_t box[2]     = {32, box_rows};                    // 64B x box_rows (SW64)
    cuuint32_t es[2]      = {1, 1};
    enc(m, CU_TENSOR_MAP_DATA_TYPE_BFLOAT16, 2, base, dims, strides, box, es,
        CU_TENSOR_MAP_INTERLEAVE_NONE, CU_TENSOR_MAP_SWIZZLE_64B,
        CU_TENSOR_MAP_L2_PROMOTION_L2_128B, CU_TENSOR_MAP_FLOAT_OOB_FILL_NONE);
}

extern "C" void kernel_launch(void* const* d_in, const int* in_sizes, int n_in,
                              void* d_out, int out_size) {
    const float* x  = (const float*)d_in[0];
    const float* E  = (const float*)d_in[1];
    // d_in[2] = eternal_biases: unused by the reference as well
    const float* W  = (const float*)d_in[3];
    const float* cb = (const float*)d_in[4];
    float* out = (float*)d_out;

    // tensormaps (host-side; recreated per call — deterministic, no device work)
    EncodeTiledFn enc = nullptr;
    cudaDriverEntryPointQueryResult qr;
    cudaGetDriverEntryPointByVersion("cuTensorMapEncodeTiled", (void**)&enc, 12000,
                                     cudaEnableDefault, &qr);
    void *pxh, *pxl, *pwh, *pwl;
    cudaGetSymbolAddress(&pxh, g_xh);
    cudaGetSymbolAddress(&pxl, g_xl);
    cudaGetSymbolAddress(&pwh, g_wh);
    cudaGetSymbolAddress(&pwl, g_wl);
    CUtensorMap mAh, mAl, mBh, mBl;
    make_map(enc, &mAh, pxh, B_DIM, 128);   // per-CTA A slice: 128 rows
    make_map(enc, &mAl, pxl, B_DIM, 128);
    make_map(enc, &mBh, pwh, M_DIM, 128);   // per-CTA B slice: 128 rows (N-split half)
    make_map(enc, &mBl, pwl, M_DIM, 128);

    cudaFuncSetAttribute(gemm_kernel, cudaFuncAttributeMaxDynamicSharedMemorySize, SMEM_TOTAL);

    prep_kernel<<<PREP_X_BLOCKS + PREP_W_BLOCKS + PREP_P_BLOCKS, 256>>>(x, W, E, cb);
    gemm_kernel<<<(B_DIM / PAIR_M) * (M_DIM / PAIR_N) * 2, THREADS, SMEM_TOTAL>>>(out, mAh, mAl, mBh, mBl);
}

// round 15
// speedup vs baseline: 1.9966x; 1.4869x over previous
#include <cuda_runtime.h>
#include <cuda.h>
#include <cuda_bf16.h>
#include <cstdint>
#include <math.h>

#define DEV_INLINE __device__ __forceinline__

// Does this compilation pass target sm_103a (arch-specific features available)?
#ifdef __CUDA_ARCH_FEAT_SM103_ALL
#define USE_TC 1
#else
#define USE_TC 0
#endif

// ---------------- problem constants ----------------
#define B_DIM 4096          // batch rows (GEMM M)
#define K_DIM 2048          // inner dim  (GEMM K)
#define M_DIM 2048          // out cols   (GEMM N)

#define THREADS 512

// ---- tcgen05 path: single CTA computes 256(M) x 256(N), 4x M128N128 sub-MMAs ----
#define CM 256
#define CN 256
#define TC_BK  32
#define TC_NT  (K_DIM / TC_BK)                 // 64
#define NSTAGE 3
// stage: Ah(16K: 256 rows x 64B) Al(16K) Bh(16K) Bl(16K) = 64KB
#define STG_AH  0
#define STG_AL  16384
#define STG_BH  32768
#define STG_BL  49152
#define STAGE_BYTES 65536
#define SMEM_TMEM_PTR 0
#define SMEM_FULL(s)  (8 + (s) * 8)            // 3 full barriers
#define SMEM_DONE(s)  (40 + (s) * 8)           // 3 done barriers
#define SMEM_FINAL    72
#define TILE_BASE     1024
#define SMEM_TOTAL    (TILE_BASE + NSTAGE * STAGE_BYTES)   // 197632

// ---- hmma fallback smem (compile-legality for the compute_103 PTX pass) ----
#define BM 128
#define BN 256
#define MM_BK         32
#define MM_NT         (K_DIM / MM_BK)              // 64
#define MM_ROWB       80                           // 64B row + 16B pad
#define MM_A_BYTES    (BM * MM_ROWB)               // 10240
#define MM_B_BYTES    (BN * MM_ROWB)               // 20480
#define MM_STAGE      (2 * MM_A_BYTES + 2 * MM_B_BYTES)  // 61440
#define MM_STAGES     3                            // 1024 + 3*61440 = 185344 <= SMEM_TOTAL

// ---------------- device scratch (allocation-free rule: __device__ globals) ----------------
__device__ __align__(16) __nv_bfloat16 g_xh[(long)B_DIM * K_DIM];
__device__ __align__(16) __nv_bfloat16 g_xl[(long)B_DIM * K_DIM];
__device__ __align__(16) __nv_bfloat16 g_wh[(long)M_DIM * K_DIM];   // [j][k] (transposed W)
__device__ __align__(16) __nv_bfloat16 g_wl[(long)M_DIM * K_DIM];
__device__ float g_bias[M_DIM];                                     // classical_bias + probs

// ---------------- PTX helpers (base-arch legal) ----------------
DEV_INLINE uint32_t smem_u32(const void* p) {
    uint32_t a;
    asm("{ .reg .u64 t; cvta.to.shared.u64 t, %1; cvt.u32.u64 %0, t; }" : "=r"(a) : "l"(p));
    return a;
}

DEV_INLINE void cp16(uint32_t dst, const void* src) {
    asm volatile("cp.async.cg.shared.global [%0], [%1], 16;" :: "r"(dst), "l"(src) : "memory");
}
DEV_INLINE void cp_commit() { asm volatile("cp.async.commit_group;" ::: "memory"); }

DEV_INLINE void ldsm4(uint32_t* r, uint32_t addr) {
    asm volatile("ldmatrix.sync.aligned.m8n8.x4.shared.b16 {%0,%1,%2,%3}, [%4];"
                 : "=r"(r[0]), "=r"(r[1]), "=r"(r[2]), "=r"(r[3]) : "r"(addr));
}
DEV_INLINE void mma16816(float* c, const uint32_t* a, uint32_t b0, uint32_t b1) {
    asm volatile("mma.sync.aligned.m16n8k16.row.col.f32.bf16.bf16.f32 "
                 "{%0,%1,%2,%3}, {%4,%5,%6,%7}, {%8,%9}, {%0,%1,%2,%3};"
                 : "+f"(c[0]), "+f"(c[1]), "+f"(c[2]), "+f"(c[3])
                 : "r"(a[0]), "r"(a[1]), "r"(a[2]), "r"(a[3]), "r"(b0), "r"(b1));
}

#if USE_TC
// ---------------- tcgen05 / TMA helpers (only in the sm_103a pass) ----------------
DEV_INLINE uint32_t elect_one() {
    uint32_t pred;
    asm volatile("{\n\t.reg .pred p;\n\telect.sync _|p, 0xFFFFFFFF;\n\t"
                 "selp.b32 %0, 1, 0, p;\n\t}" : "=r"(pred));
    return pred;
}
#define MBAR_INIT(addr, cnt) \
    asm volatile("mbarrier.init.shared.b64 [%0], %1;" :: "r"(addr), "r"(cnt) : "memory")
#define MBAR_INVAL(addr) \
    asm volatile("mbarrier.inval.shared.b64 [%0];" :: "r"(addr) : "memory")
#define MBAR_EXPECT_TX(addr, tx) \
    asm volatile("mbarrier.arrive.expect_tx.shared.b64 _, [%0], %1;" \
                 :: "r"(addr), "r"((uint32_t)(tx)) : "memory")

DEV_INLINE void mbar_wait(uint32_t mbar, uint32_t parity) {
    uint32_t done;
    asm volatile("{\n\t.reg .pred p;\n\t"
                 "mbarrier.try_wait.parity.acquire.cta.shared::cta.b64 p, [%1], %2;\n\t"
                 "selp.b32 %0, 1, 0, p;\n\t}"
                 : "=r"(done) : "r"(mbar), "r"(parity) : "memory");
    if (!done) {
        asm volatile("{\n\t.reg .pred P1;\n\t"
                     "W_%=:\n\t"
                     "mbarrier.try_wait.parity.acquire.cta.shared::cta.b64 P1, [%0], %1, 0x989680;\n\t"
                     "@P1 bra.uni D_%=;\n\t"
                     "bra.uni W_%=;\n\t"
                     "D_%=:\n\t}"
                     :: "r"(mbar), "r"(parity) : "memory");
    }
}

#define TCGEN05_ALLOC(sm_addr, nc) \
    asm volatile("tcgen05.alloc.cta_group::1.sync.aligned.shared::cta.b32 [%0], %1;" \
                 :: "r"((uint32_t)(sm_addr)), "r"((uint32_t)(nc)) : "memory")
#define TCGEN05_DEALLOC(tmem, nc) \
    asm volatile("tcgen05.dealloc.cta_group::1.sync.aligned.b32 %0, %1;" :: "r"(tmem), "r"(nc))
#define TCGEN05_COMMIT(mbar) \
    asm volatile("tcgen05.commit.cta_group::1.mbarrier::arrive::one.shared::cluster.b64 [%0];" \
                 :: "r"((uint32_t)(mbar)) : "memory")
#define TCGEN05_FENCE_AFTER()  asm volatile("tcgen05.fence::after_thread_sync;" ::: "memory")
#define TCGEN05_FENCE_BEFORE() asm volatile("tcgen05.fence::before_thread_sync;" ::: "memory")
#define TCGEN05_WAIT_LD()      asm volatile("tcgen05.wait::ld.sync.aligned;" ::: "memory")

#define TCGEN05_LD_X32(r, ta) \
    asm volatile("tcgen05.ld.sync.aligned.32x32b.x32.b32 " \
        "{%0, %1, %2, %3, %4, %5, %6, %7, %8, %9, %10, %11, %12, %13, %14, %15, " \
        " %16, %17, %18, %19, %20, %21, %22, %23, %24, %25, %26, %27, %28, %29, %30, %31}, [%32];" \
        : "=r"((r)[0]),  "=r"((r)[1]),  "=r"((r)[2]),  "=r"((r)[3]), \
          "=r"((r)[4]),  "=r"((r)[5]),  "=r"((r)[6]),  "=r"((r)[7]), \
          "=r"((r)[8]),  "=r"((r)[9]),  "=r"((r)[10]), "=r"((r)[11]), \
          "=r"((r)[12]), "=r"((r)[13]), "=r"((r)[14]), "=r"((r)[15]), \
          "=r"((r)[16]), "=r"((r)[17]), "=r"((r)[18]), "=r"((r)[19]), \
          "=r"((r)[20]), "=r"((r)[21]), "=r"((r)[22]), "=r"((r)[23]), \
          "=r"((r)[24]), "=r"((r)[25]), "=r"((r)[26]), "=r"((r)[27]), \
          "=r"((r)[28]), "=r"((r)[29]), "=r"((r)[30]), "=r"((r)[31]) \
        : "r"(ta))

// SW64 K-major descriptor: layout=4, version=1, SBO=32 (8 rows x 64B = 512B), LBO=1
static constexpr uint64_t DESC_BASE_SW64 =
    (uint64_t(4) << 61) | (uint64_t(1) << 46) | (uint64_t(32) << 32) | (uint64_t(1) << 16);
DEV_INLINE uint64_t make_desc64(uint32_t addr) {
    return DESC_BASE_SW64 | ((uint64_t)(addr >> 4) & 0x3FFF);
}
// idesc kind::f16: fp32 acc, bf16 A, bf16 B, M=128, N=128 (per sub-MMA)
#define MMA_IDESC ((1u << 4) | (1u << 7) | (1u << 10) | ((128u / 8u) << 17) | ((128u / 16u) << 24))

DEV_INLINE void mma_bf16_ss(uint32_t d_tmem, uint64_t a_desc, uint64_t b_desc, uint32_t en) {
    asm volatile("{\n\t.reg .pred p;\n\tsetp.ne.u32 p, %4, 0;\n\t"
                 "tcgen05.mma.cta_group::1.kind::f16 [%0], %1, %2, %3, {%5, %5, %5, %5}, p;\n\t}"
                 :: "r"(d_tmem), "l"(a_desc), "l"(b_desc), "r"(MMA_IDESC),
                    "r"(en), "r"(0u)
                 : "memory");
}

// 2D TMA load, CTA-local
DEV_INLINE void tma2d(uint32_t dst, const CUtensorMap* map, int x, int y, uint32_t mbar) {
    asm volatile("cp.async.bulk.tensor.2d.shared::cta.global.tile.mbarrier::complete_tx::bytes "
                 "[%0], [%1, {%2, %3}], [%4];"
                 :: "r"(dst), "l"(map), "r"(x), "r"(y), "r"(mbar) : "memory");
}
#endif // USE_TC

// ---------------- split helpers ----------------
DEV_INLINE void split1(float v, __nv_bfloat16& h, __nv_bfloat16& l) {
    h = __float2bfloat16(v);
    l = __float2bfloat16(v - __bfloat162float(h));
}

// ---------------- fused prep kernel: split_x + transpose-split_w + probs ----------------
#define PREP_X_BLOCKS 8192     // 8M elems, 4/thread, 256 thr
#define PREP_W_BLOCKS 4096     // 64 x 64 tiles of 32x32
#define PREP_P_BLOCKS 8        // 2048 cols / 256
__global__ void prep_kernel(const float* __restrict__ x, const float* __restrict__ W,
                            const float* __restrict__ E, const float* __restrict__ cb) {
    int b = blockIdx.x;
    int tid = threadIdx.x;
    if (b < PREP_X_BLOCKS) {
        // ---- split x ----
        long i = ((long)b * 256 + tid) * 4;
        float4 v = *(const float4*)(x + i);
        __nv_bfloat16 h0, h1, h2, h3, l0, l1, l2, l3;
        split1(v.x, h0, l0); split1(v.y, h1, l1); split1(v.z, h2, l2); split1(v.w, h3, l3);
        ushort4 hv, lv;
        hv.x = __bfloat16_as_ushort(h0); hv.y = __bfloat16_as_ushort(h1);
        hv.z = __bfloat16_as_ushort(h2); hv.w = __bfloat16_as_ushort(h3);
        lv.x = __bfloat16_as_ushort(l0); lv.y = __bfloat16_as_ushort(l1);
        lv.z = __bfloat16_as_ushort(l2); lv.w = __bfloat16_as_ushort(l3);
        *(ushort4*)((unsigned short*)g_xh + i) = hv;
        *(ushort4*)((unsigned short*)g_xl + i) = lv;
    } else if (b < PREP_X_BLOCKS + PREP_W_BLOCKS) {
        // ---- transpose-split W ----
        __shared__ float t[32][33];
        int wb = b - PREP_X_BLOCKS;
        int j0 = (wb & 63) * 32, k0 = (wb >> 6) * 32;
        int tx = tid & 31, ty = tid >> 5;     // 32 x 8
#pragma unroll
        for (int r = ty; r < 32; r += 8)
            t[r][tx] = W[(long)(k0 + r) * M_DIM + j0 + tx];
        __syncthreads();
#pragma unroll
        for (int r = ty; r < 32; r += 8) {
            float v = t[tx][r];               // = W[k0+tx][j0+r]
            __nv_bfloat16 h, l; split1(v, h, l);
            long o = (long)(j0 + r) * K_DIM + k0 + tx;
            g_wh[o] = h; g_wl[o] = l;
        }
    } else {
        // ---- probs + bias fold: probs[j] = (1/K) * prod cos^2(E[d,j,g]) ----
        int j = (b - PREP_X_BLOCKS - PREP_W_BLOCKS) * 256 + tid;
        if (j < M_DIM) {
            float p = 1.0f;
#pragma unroll
            for (int d = 0; d < 9; d++)
#pragma unroll
                for (int g = 0; g < 3; g++) {
                    float a = E[(long)d * K_DIM * M_DIM + (long)j * M_DIM + g];
                    float c = cosf(a);
                    p *= c * c;
                }
            g_bias[j] = cb[j] + p * (1.0f / (float)K_DIM);
        }
    }
}

#if !USE_TC
// ---------------- hmma tile loader (fallback pass only) ----------------
DEV_INLINE void load_tile_mm(uint32_t smem_base, int stage, int kt, int tileM, int tileN, int tid) {
    uint32_t sb = smem_base + TILE_BASE + stage * MM_STAGE;
#pragma unroll
    for (int i = tid; i < 3072; i += THREADS) {
        if (i < 1024) {
            int hl = i >> 9;
            int t = i & 511; int r = t >> 2, c = t & 3;
            uint32_t dst = sb + hl * MM_A_BYTES + r * MM_ROWB + c * 16;
            long src = (long)(tileM * BM + r) * (K_DIM * 2) + (long)kt * (MM_BK * 2) + c * 16;
            cp16(dst, (const char*)(hl ? (const void*)g_xl : (const void*)g_xh) + src);
        } else {
            int j = i - 1024; int hl = j >> 10;
            int t = j & 1023; int r = t >> 2, c = t & 3;
            uint32_t dst = sb + 2 * MM_A_BYTES + hl * MM_B_BYTES + r * MM_ROWB + c * 16;
            long src = (long)(tileN * BN + r) * (K_DIM * 2) + (long)kt * (MM_BK * 2) + c * 16;
            cp16(dst, (const char*)(hl ? (const void*)g_wl : (const void*)g_wh) + src);
        }
    }
    cp_commit();
}
#endif

// ---------------- main GEMM: warp-specialized TMA + tcgen05, 256x256 single-CTA tile ----------------
__global__ void __launch_bounds__(THREADS, 1)
gemm_kernel(float* __restrict__ out,
            const __grid_constant__ CUtensorMap mAh,
            const __grid_constant__ CUtensorMap mAl,
            const __grid_constant__ CUtensorMap mBh,
            const __grid_constant__ CUtensorMap mBl) {
    extern __shared__ char smem[];
    uint32_t smem_base = smem_u32(smem);
    int tid = threadIdx.x;
    int wid = tid >> 5, lid = tid & 31;
    int bid = blockIdx.x;

#if USE_TC
    // ================= tcgen05 path: 256x256 tile, 24 M128N128K16 MMAs/iter =================
    int tileM = bid & 15;        // 16 tileM values; consecutive bids share tileN band
    int tileN = bid >> 4;        // 0..7

    if (wid == 0) TCGEN05_ALLOC(smem_base + SMEM_TMEM_PTR, 512);
    if (tid == 0) {
#pragma unroll
        for (int s = 0; s < NSTAGE; ++s) {
            MBAR_INIT(smem_base + SMEM_FULL(s), 1);   // arrive: producer expect_tx
            MBAR_INIT(smem_base + SMEM_DONE(s), 1);   // arrive: MMA commit
        }
        MBAR_INIT(smem_base + SMEM_FINAL, 1);
    }
    __syncthreads();
    uint32_t tmem;
    asm volatile("ld.shared.b32 %0, [%1];" : "=r"(tmem) : "r"(smem_base + SMEM_TMEM_PTR));

    uint32_t epred = elect_one();

    if (wid == 1 && epred) {
        // ---- producer: 4 TMAs per stage (256-row boxes), paced by MMA completion ----
        int arow = tileM * CM;
        int brow = tileN * CN;
        for (int kt = 0; kt < TC_NT; ++kt) {
            int s = kt % NSTAGE;
            uint32_t fb = smem_base + SMEM_FULL(s);
            if (kt >= NSTAGE)
                mbar_wait(smem_base + SMEM_DONE(s), ((kt - NSTAGE) / NSTAGE) & 1);
            MBAR_EXPECT_TX(fb, STAGE_BYTES);
            uint32_t sa = smem_base + TILE_BASE + s * STAGE_BYTES;
            int kx = kt * TC_BK;
            tma2d(sa + STG_AH, &mAh, kx, arow, fb);
            tma2d(sa + STG_AL, &mAl, kx, arow, fb);
            tma2d(sa + STG_BH, &mBh, kx, brow, fb);
            tma2d(sa + STG_BL, &mBl, kx, brow, fb);
        }
    } else if (wid == 0 && epred) {
        // ---- consumer: 24 MMAs per stage (2 mh x 2 ks x 2 nh x 3 products) ----
        for (int kt = 0; kt < TC_NT; ++kt) {
            int s = kt % NSTAGE;
            mbar_wait(smem_base + SMEM_FULL(s), (kt / NSTAGE) & 1);

            uint32_t sa  = smem_base + TILE_BASE + s * STAGE_BYTES;
            uint64_t dah = make_desc64(sa + STG_AH);
            uint64_t dal = make_desc64(sa + STG_AL);
            uint64_t dbh = make_desc64(sa + STG_BH);
            uint64_t dbl = make_desc64(sa + STG_BL);
#pragma unroll
            for (int mh = 0; mh < 2; ++mh) {               // M halves (128 rows each)
                uint64_t am = (uint64_t)(mh * 512);        // 128 rows * 64B = 8KB = 512 units
#pragma unroll
                for (int ks = 0; ks < 2; ++ks) {           // K=16 per MMA, 2 steps (BK=32)
                    uint64_t o = (uint64_t)(ks * 2);       // 32B = 2 desc units
#pragma unroll
                    for (int nh = 0; nh < 2; ++nh) {       // N halves (128 cols each)
                        uint64_t bo = o + (uint64_t)(nh * 512);
                        uint32_t dd = tmem + mh * 256 + nh * 128;
                        uint32_t acc = (kt > 0) || (ks > 0);
                        mma_bf16_ss(dd, dah + am + o, dbh + bo, acc);  // hi*hi
                        mma_bf16_ss(dd, dah + am + o, dbl + bo, 1u);   // hi*lo
                        mma_bf16_ss(dd, dal + am + o, dbh + bo, 1u);   // lo*hi
                    }
                }
            }
            TCGEN05_COMMIT(smem_base + SMEM_DONE(s));
        }
        TCGEN05_COMMIT(smem_base + SMEM_FINAL);        // tracks ALL prior MMAs
    }

    // Everyone: wait for all MMAs (count=1, first phase).
    mbar_wait(smem_base + SMEM_FINAL, 0);
    TCGEN05_FENCE_AFTER();

    // Epilogue: 16 warps. wid>>3 = M-half; (wid&7): &3 = subpartition, >>2 = col half.
    // Each warp: 32 lanes x 128 cols (4x LD_X32).
    {
        int mh   = wid >> 3;
        int wg   = wid & 7;
        int sub  = wg & 3;
        int ch   = wg >> 2;
        long gm  = (long)tileM * CM + mh * 128 + sub * 32 + lid;
#pragma unroll
        for (int cc = 0; cc < 4; ++cc) {
            uint32_t d[32];
            TCGEN05_LD_X32(d, tmem + mh * 256 + ch * 128 + cc * 32);
            TCGEN05_WAIT_LD();
            int gc = tileN * CN + ch * 128 + cc * 32;
            const float4* bp = (const float4*)(g_bias + gc);
            float4* op = (float4*)(out + gm * M_DIM + gc);
#pragma unroll
            for (int q = 0; q < 8; ++q) {
                float4 b = bp[q];
                float4 o;
                o.x = tanhf(__uint_as_float(d[q * 4 + 0]) + b.x);
                o.y = tanhf(__uint_as_float(d[q * 4 + 1]) + b.y);
                o.z = tanhf(__uint_as_float(d[q * 4 + 2]) + b.z);
                o.w = tanhf(__uint_as_float(d[q * 4 + 3]) + b.w);
                op[q] = o;
            }
        }
        TCGEN05_FENCE_BEFORE();
    }

    __syncthreads();
    if (tid == 0) {
#pragma unroll
        for (int s = 0; s < NSTAGE; ++s) {
            MBAR_INVAL(smem_base + SMEM_FULL(s));
            MBAR_INVAL(smem_base + SMEM_DONE(s));
        }
        MBAR_INVAL(smem_base + SMEM_FINAL);
    }
    __syncthreads();
    if (wid == 0) TCGEN05_DEALLOC(tmem, 512);

#else
    // ================= HMMA fallback (base-PTX legal; never runs on GB300) =================
    // CTA covers 256x256 as two sequential 128x256 halves.
    int tileN = bid >> 4;
    int wr = wid & 3;
    int wc = wid >> 2;
    const int lrow = lid & 15;
    const int lk16b = (lid >> 4) * 16;

    for (int mh = 0; mh < 2; ++mh) {
        int tileM = (bid & 15) * 2 + mh;

        float acc[2][8][4];
#pragma unroll
        for (int mt = 0; mt < 2; ++mt)
#pragma unroll
            for (int nt = 0; nt < 8; ++nt)
#pragma unroll
                for (int q = 0; q < 4; ++q) acc[mt][nt][q] = 0.0f;

        load_tile_mm(smem_base, 0, 0, tileM, tileN, tid);
        load_tile_mm(smem_base, 1, 1, tileM, tileN, tid);
        load_tile_mm(smem_base, 2, 2, tileM, tileN, tid);

        for (int kt = 0; kt < MM_NT; ++kt) {
            asm volatile("cp.async.wait_group 2;" ::: "memory");
            __syncthreads();

            int s = kt % MM_STAGES;
            uint32_t sb  = smem_base + TILE_BASE + s * MM_STAGE;
            uint32_t sAh = sb;
            uint32_t sAl = sb + MM_A_BYTES;
            uint32_t sBh = sb + 2 * MM_A_BYTES;
            uint32_t sBl = sb + 2 * MM_A_BYTES + MM_B_BYTES;

#pragma unroll
            for (int k16 = 0; k16 < 2; ++k16) {
                uint32_t koff = k16 * 32 + lk16b;
                uint32_t aoff = (uint32_t)(wr * 32 + lrow) * MM_ROWB + koff;
                uint32_t boff = (uint32_t)(wc * 64 + lrow) * MM_ROWB + koff;

                uint32_t ah[2][4], bh[4][4];
                ldsm4(ah[0], sAh + aoff);
                ldsm4(ah[1], sAh + aoff + 16 * MM_ROWB);
#pragma unroll
                for (int g = 0; g < 4; ++g) ldsm4(bh[g], sBh + boff + g * 16 * MM_ROWB);

#pragma unroll
                for (int mt = 0; mt < 2; ++mt)
#pragma unroll
                    for (int nt = 0; nt < 8; ++nt)
                        mma16816(acc[mt][nt], ah[mt], bh[nt >> 1][nt & 1], bh[nt >> 1][(nt & 1) + 2]);

                uint32_t al[2][4];
                ldsm4(al[0], sAl + aoff);
                ldsm4(al[1], sAl + aoff + 16 * MM_ROWB);
#pragma unroll
                for (int mt = 0; mt < 2; ++mt)
#pragma unroll
                    for (int nt = 0; nt < 8; ++nt)
                        mma16816(acc[mt][nt], al[mt], bh[nt >> 1][nt & 1], bh[nt >> 1][(nt & 1) + 2]);

                uint32_t bl[4][4];
#pragma unroll
                for (int g = 0; g < 4; ++g) ldsm4(bl[g], sBl + boff + g * 16 * MM_ROWB);
#pragma unroll
                for (int mt = 0; mt < 2; ++mt)
#pragma unroll
                    for (int nt = 0; nt < 8; ++nt)
                        mma16816(acc[mt][nt], ah[mt], bl[nt >> 1][nt & 1], bl[nt >> 1][(nt & 1) + 2]);
            }

            __syncthreads();
            if (kt + MM_STAGES < MM_NT)
                load_tile_mm(smem_base, s, kt + MM_STAGES, tileM, tileN, tid);
        }

        {
            int r0 = tileM * BM + wr * 32 + (lid >> 2);
            int c0 = tileN * BN + wc * 64 + (lid & 3) * 2;
#pragma unroll
            for (int mt = 0; mt < 2; ++mt) {
#pragma unroll
                for (int nt = 0; nt < 8; ++nt) {
                    int row = r0 + mt * 16;
                    int col = c0 + nt * 8;
                    float2 bv = *(const float2*)(g_bias + col);
                    float2 o0, o1;
                    o0.x = tanhf(acc[mt][nt][0] + bv.x);
                    o0.y = tanhf(acc[mt][nt][1] + bv.y);
                    o1.x = tanhf(acc[mt][nt][2] + bv.x);
                    o1.y = tanhf(acc[mt][nt][3] + bv.y);
                    *(float2*)(out + (long)row * M_DIM + col) = o0;
                    *(float2*)(out + (long)(row + 8) * M_DIM + col) = o1;
                }
            }
        }
        __syncthreads();
    }
#endif
}

// ---------------- host: tensormap creation via driver entry point ----------------
typedef CUresult (*EncodeTiledFn)(
    CUtensorMap*, CUtensorMapDataType, cuuint32_t, void*,
    const cuuint64_t*, const cuuint64_t*, const cuuint32_t*, const cuuint32_t*,
    CUtensorMapInterleave, CUtensorMapSwizzle, CUtensorMapL2promotion, CUtensorMapFloatOOBfill);

static void make_map(EncodeTiledFn enc, CUtensorMap* m, void* base,
                     unsigned long long rows, unsigned box_rows) {
    cuuint64_t dims[2]    = {(cuuint64_t)K_DIM, (cuuint64_t)rows};
    cuuint64_t strides[1] = {(cuuint64_t)K_DIM * 2};           // bytes between rows
    cuuint32_t box[2]     = {32, box_rows};                    // 64B x box_rows (SW64)
    cuuint32_t es[2]      = {1, 1};
    enc(m, CU_TENSOR_MAP_DATA_TYPE_BFLOAT16, 2, base, dims, strides, box, es,
        CU_TENSOR_MAP_INTERLEAVE_NONE, CU_TENSOR_MAP_SWIZZLE_64B,
        CU_TENSOR_MAP_L2_PROMOTION_L2_128B, CU_TENSOR_MAP_FLOAT_OOB_FILL_NONE);
}

extern "C" void kernel_launch(void* const* d_in, const int* in_sizes, int n_in,
                              void* d_out, int out_size) {
    const float* x  = (const float*)d_in[0];
    const float* E  = (const float*)d_in[1];
    // d_in[2] = eternal_biases: unused by the reference as well
    const float* W  = (const float*)d_in[3];
    const float* cb = (const float*)d_in[4];
    float* out = (float*)d_out;

    // tensormaps (host-side; recreated per call — deterministic, no device work)
    EncodeTiledFn enc = nullptr;
    cudaDriverEntryPointQueryResult qr;
    cudaGetDriverEntryPointByVersion("cuTensorMapEncodeTiled", (void**)&enc, 12000,
                                     cudaEnableDefault, &qr);
    void *pxh, *pxl, *pwh, *pwl;
    cudaGetSymbolAddress(&pxh, g_xh);
    cudaGetSymbolAddress(&pxl, g_xl);
    cudaGetSymbolAddress(&pwh, g_wh);
    cudaGetSymbolAddress(&pwl, g_wl);
    CUtensorMap mAh, mAl, mBh, mBl;
    make_map(enc, &mAh, pxh, B_DIM, 256);   // A: 256-row boxes
    make_map(enc, &mAl, pxl, B_DIM, 256);
    make_map(enc, &mBh, pwh, M_DIM, 256);   // B: 256-row boxes
    make_map(enc, &mBl, pwl, M_DIM, 256);

    cudaFuncSetAttribute(gemm_kernel, cudaFuncAttributeMaxDynamicSharedMemorySize, SMEM_TOTAL);

    prep_kernel<<<PREP_X_BLOCKS + PREP_W_BLOCKS + PREP_P_BLOCKS, 256>>>(x, W, E, cb);
    gemm_kernel<<<(B_DIM / CM) * (M_DIM / CN), THREADS, SMEM_TOTAL>>>(out, mAh, mAl, mBh, mBl);
}

// round 17
// speedup vs baseline: 2.0053x; 1.0044x over previous
#include <cuda_runtime.h>
#include <cuda.h>
#include <cuda_bf16.h>
#include <cstdint>
#include <math.h>

#define DEV_INLINE __device__ __forceinline__

// Does this compilation pass target sm_103a (arch-specific features available)?
#ifdef __CUDA_ARCH_FEAT_SM103_ALL
#define USE_TC 1
#else
#define USE_TC 0
#endif

// ---------------- problem constants ----------------
#define B_DIM 4096          // batch rows (GEMM M)
#define K_DIM 2048          // inner dim  (GEMM K)
#define M_DIM 2048          // out cols   (GEMM N)

#define THREADS 512

// ---- tcgen05 path: single CTA computes 256(M) x 256(N); M128xN256 dispatches ----
#define CM 256
#define CN 256
#define TC_BK  32
#define TC_NT  (K_DIM / TC_BK)                 // 64
#define NSTAGE 3
// stage: Ah(16K: 256 rows x 64B) Al(16K) Bh(16K) Bl(16K) = 64KB
#define STG_AH  0
#define STG_AL  16384
#define STG_BH  32768
#define STG_BL  49152
#define STAGE_BYTES 65536
#define SMEM_TMEM_PTR 0
#define SMEM_FULL(s)  (8 + (s) * 8)            // 3 full barriers
#define SMEM_DONE(s)  (40 + (s) * 8)           // 3 done barriers
#define SMEM_FINAL    72
#define TILE_BASE     1024
#define SMEM_TOTAL    (TILE_BASE + NSTAGE * STAGE_BYTES)   // 197632

// ---- hmma fallback smem (compile-legality for the compute_103 PTX pass) ----
#define BM 128
#define BN 256
#define MM_BK         32
#define MM_NT         (K_DIM / MM_BK)              // 64
#define MM_ROWB       80                           // 64B row + 16B pad
#define MM_A_BYTES    (BM * MM_ROWB)               // 10240
#define MM_B_BYTES    (BN * MM_ROWB)               // 20480
#define MM_STAGE      (2 * MM_A_BYTES + 2 * MM_B_BYTES)  // 61440
#define MM_STAGES     3                            // 1024 + 3*61440 = 185344 <= SMEM_TOTAL

// ---------------- device scratch (allocation-free rule: __device__ globals) ----------------
__device__ __align__(16) __nv_bfloat16 g_xh[(long)B_DIM * K_DIM];
__device__ __align__(16) __nv_bfloat16 g_xl[(long)B_DIM * K_DIM];
__device__ __align__(16) __nv_bfloat16 g_wh[(long)M_DIM * K_DIM];   // [j][k] (transposed W)
__device__ __align__(16) __nv_bfloat16 g_wl[(long)M_DIM * K_DIM];
__device__ float g_bias[M_DIM];                                     // classical_bias + probs

// ---------------- PTX helpers (base-arch legal) ----------------
DEV_INLINE uint32_t smem_u32(const void* p) {
    uint32_t a;
    asm("{ .reg .u64 t; cvta.to.shared.u64 t, %1; cvt.u32.u64 %0, t; }" : "=r"(a) : "l"(p));
    return a;
}

DEV_INLINE void cp16(uint32_t dst, const void* src) {
    asm volatile("cp.async.cg.shared.global [%0], [%1], 16;" :: "r"(dst), "l"(src) : "memory");
}
DEV_INLINE void cp_commit() { asm volatile("cp.async.commit_group;" ::: "memory"); }

DEV_INLINE void ldsm4(uint32_t* r, uint32_t addr) {
    asm volatile("ldmatrix.sync.aligned.m8n8.x4.shared.b16 {%0,%1,%2,%3}, [%4];"
                 : "=r"(r[0]), "=r"(r[1]), "=r"(r[2]), "=r"(r[3]) : "r"(addr));
}
DEV_INLINE void mma16816(float* c, const uint32_t* a, uint32_t b0, uint32_t b1) {
    asm volatile("mma.sync.aligned.m16n8k16.row.col.f32.bf16.bf16.f32 "
                 "{%0,%1,%2,%3}, {%4,%5,%6,%7}, {%8,%9}, {%0,%1,%2,%3};"
                 : "+f"(c[0]), "+f"(c[1]), "+f"(c[2]), "+f"(c[3])
                 : "r"(a[0]), "r"(a[1]), "r"(a[2]), "r"(a[3]), "r"(b0), "r"(b1));
}

#if USE_TC
// ---------------- tcgen05 / TMA helpers (only in the sm_103a pass) ----------------
DEV_INLINE uint32_t elect_one() {
    uint32_t pred;
    asm volatile("{\n\t.reg .pred p;\n\telect.sync _|p, 0xFFFFFFFF;\n\t"
                 "selp.b32 %0, 1, 0, p;\n\t}" : "=r"(pred));
    return pred;
}
#define MBAR_INIT(addr, cnt) \
    asm volatile("mbarrier.init.shared.b64 [%0], %1;" :: "r"(addr), "r"(cnt) : "memory")
#define MBAR_INVAL(addr) \
    asm volatile("mbarrier.inval.shared.b64 [%0];" :: "r"(addr) : "memory")
#define MBAR_EXPECT_TX(addr, tx) \
    asm volatile("mbarrier.arrive.expect_tx.shared.b64 _, [%0], %1;" \
                 :: "r"(addr), "r"((uint32_t)(tx)) : "memory")

DEV_INLINE void mbar_wait(uint32_t mbar, uint32_t parity) {
    uint32_t done;
    asm volatile("{\n\t.reg .pred p;\n\t"
                 "mbarrier.try_wait.parity.acquire.cta.shared::cta.b64 p, [%1], %2;\n\t"
                 "selp.b32 %0, 1, 0, p;\n\t}"
                 : "=r"(done) : "r"(mbar), "r"(parity) : "memory");
    if (!done) {
        asm volatile("{\n\t.reg .pred P1;\n\t"
                     "W_%=:\n\t"
                     "mbarrier.try_wait.parity.acquire.cta.shared::cta.b64 P1, [%0], %1, 0x989680;\n\t"
                     "@P1 bra.uni D_%=;\n\t"
                     "bra.uni W_%=;\n\t"
                     "D_%=:\n\t}"
                     :: "r"(mbar), "r"(parity) : "memory");
    }
}

#define TCGEN05_ALLOC(sm_addr, nc) \
    asm volatile("tcgen05.alloc.cta_group::1.sync.aligned.shared::cta.b32 [%0], %1;" \
                 :: "r"((uint32_t)(sm_addr)), "r"((uint32_t)(nc)) : "memory")
#define TCGEN05_DEALLOC(tmem, nc) \
    asm volatile("tcgen05.dealloc.cta_group::1.sync.aligned.b32 %0, %1;" :: "r"(tmem), "r"(nc))
#define TCGEN05_COMMIT(mbar) \
    asm volatile("tcgen05.commit.cta_group::1.mbarrier::arrive::one.shared::cluster.b64 [%0];" \
                 :: "r"((uint32_t)(mbar)) : "memory")
#define TCGEN05_FENCE_AFTER()  asm volatile("tcgen05.fence::after_thread_sync;" ::: "memory")
#define TCGEN05_FENCE_BEFORE() asm volatile("tcgen05.fence::before_thread_sync;" ::: "memory")
#define TCGEN05_WAIT_LD()      asm volatile("tcgen05.wait::ld.sync.aligned;" ::: "memory")

#define TCGEN05_LD_X32(r, ta) \
    asm volatile("tcgen05.ld.sync.aligned.32x32b.x32.b32 " \
        "{%0, %1, %2, %3, %4, %5, %6, %7, %8, %9, %10, %11, %12, %13, %14, %15, " \
        " %16, %17, %18, %19, %20, %21, %22, %23, %24, %25, %26, %27, %28, %29, %30, %31}, [%32];" \
        : "=r"((r)[0]),  "=r"((r)[1]),  "=r"((r)[2]),  "=r"((r)[3]), \
          "=r"((r)[4]),  "=r"((r)[5]),  "=r"((r)[6]),  "=r"((r)[7]), \
          "=r"((r)[8]),  "=r"((r)[9]),  "=r"((r)[10]), "=r"((r)[11]), \
          "=r"((r)[12]), "=r"((r)[13]), "=r"((r)[14]), "=r"((r)[15]), \
          "=r"((r)[16]), "=r"((r)[17]), "=r"((r)[18]), "=r"((r)[19]), \
          "=r"((r)[20]), "=r"((r)[21]), "=r"((r)[22]), "=r"((r)[23]), \
          "=r"((r)[24]), "=r"((r)[25]), "=r"((r)[26]), "=r"((r)[27]), \
          "=r"((r)[28]), "=r"((r)[29]), "=r"((r)[30]), "=r"((r)[31]) \
        : "r"(ta))

// SW64 K-major descriptor: layout=4, version=1, SBO=32 (8 rows x 64B = 512B), LBO=1
static constexpr uint64_t DESC_BASE_SW64 =
    (uint64_t(4) << 61) | (uint64_t(1) << 46) | (uint64_t(32) << 32) | (uint64_t(1) << 16);
DEV_INLINE uint64_t make_desc64(uint32_t addr) {
    return DESC_BASE_SW64 | ((uint64_t)(addr >> 4) & 0x3FFF);
}
// idesc kind::f16: fp32 acc, bf16 A, bf16 B, M=128, N=256 per dispatch
#define MMA_IDESC ((1u << 4) | (1u << 7) | (1u << 10) | ((256u / 8u) << 17) | ((128u / 16u) << 24))

DEV_INLINE void mma_bf16_ss(uint32_t d_tmem, uint64_t a_desc, uint64_t b_desc, uint32_t en) {
    asm volatile("{\n\t.reg .pred p;\n\tsetp.ne.u32 p, %4, 0;\n\t"
                 "tcgen05.mma.cta_group::1.kind::f16 [%0], %1, %2, %3, {%5, %5, %5, %5}, p;\n\t}"
                 :: "r"(d_tmem), "l"(a_desc), "l"(b_desc), "r"(MMA_IDESC),
                    "r"(en), "r"(0u)
                 : "memory");
}

// 2D TMA load, CTA-local
DEV_INLINE void tma2d(uint32_t dst, const CUtensorMap* map, int x, int y, uint32_t mbar) {
    asm volatile("cp.async.bulk.tensor.2d.shared::cta.global.tile.mbarrier::complete_tx::bytes "
                 "[%0], [%1, {%2, %3}], [%4];"
                 :: "r"(dst), "l"(map), "r"(x), "r"(y), "r"(mbar) : "memory");
}
#endif // USE_TC

// ---------------- split helpers ----------------
DEV_INLINE void split1(float v, __nv_bfloat16& h, __nv_bfloat16& l) {
    h = __float2bfloat16(v);
    l = __float2bfloat16(v - __bfloat162float(h));
}

// ---------------- fused prep kernel: split_x + transpose-split_w + probs ----------------
#define PREP_X_BLOCKS 4096     // 8M elems, 8/thread, 256 thr
#define PREP_W_BLOCKS 2048     // 32 k-tiles(64) x 64 j-tiles(32)
#define PREP_P_BLOCKS 8        // 2048 cols / 256
__global__ void prep_kernel(const float* __restrict__ x, const float* __restrict__ W,
                            const float* __restrict__ E, const float* __restrict__ cb) {
    int b = blockIdx.x;
    int tid = threadIdx.x;
    if (b < PREP_X_BLOCKS) {
        // ---- split x: 8 elems/thread, 16B stores ----
        long i = ((long)b * 256 + tid) * 8;
        float4 v0 = *(const float4*)(x + i);
        float4 v1 = *(const float4*)(x + i + 4);
        __nv_bfloat16 h[8], l[8];
        split1(v0.x, h[0], l[0]); split1(v0.y, h[1], l[1]);
        split1(v0.z, h[2], l[2]); split1(v0.w, h[3], l[3]);
        split1(v1.x, h[4], l[4]); split1(v1.y, h[5], l[5]);
        split1(v1.z, h[6], l[6]); split1(v1.w, h[7], l[7]);
        uint4 hv, lv;
        hv.x = (uint32_t)__bfloat16_as_ushort(h[0]) | ((uint32_t)__bfloat16_as_ushort(h[1]) << 16);
        hv.y = (uint32_t)__bfloat16_as_ushort(h[2]) | ((uint32_t)__bfloat16_as_ushort(h[3]) << 16);
        hv.z = (uint32_t)__bfloat16_as_ushort(h[4]) | ((uint32_t)__bfloat16_as_ushort(h[5]) << 16);
        hv.w = (uint32_t)__bfloat16_as_ushort(h[6]) | ((uint32_t)__bfloat16_as_ushort(h[7]) << 16);
        lv.x = (uint32_t)__bfloat16_as_ushort(l[0]) | ((uint32_t)__bfloat16_as_ushort(l[1]) << 16);
        lv.y = (uint32_t)__bfloat16_as_ushort(l[2]) | ((uint32_t)__bfloat16_as_ushort(l[3]) << 16);
        lv.z = (uint32_t)__bfloat16_as_ushort(l[4]) | ((uint32_t)__bfloat16_as_ushort(l[5]) << 16);
        lv.w = (uint32_t)__bfloat16_as_ushort(l[6]) | ((uint32_t)__bfloat16_as_ushort(l[7]) << 16);
        *(uint4*)((unsigned short*)g_xh + i) = hv;
        *(uint4*)((unsigned short*)g_xl + i) = lv;
    } else if (b < PREP_X_BLOCKS + PREP_W_BLOCKS) {
        // ---- transpose-split W: 64k x 32j tile; 128B-contiguous writes per warp ----
        __shared__ float t[64][33];
        int wb = b - PREP_X_BLOCKS;
        int j0 = (wb & 63) * 32;          // 64 j-tiles
        int k0 = (wb >> 6) * 64;          // 32 k-tiles
        int tx = tid & 31, ty = tid >> 5; // 8 warps
#pragma unroll
        for (int kk = ty; kk < 64; kk += 8)
            t[kk][tx] = W[(long)(k0 + kk) * M_DIM + j0 + tx];
        __syncthreads();
#pragma unroll
        for (int jj = ty; jj < 32; jj += 8) {
            float va = t[2 * tx][jj], vb = t[2 * tx + 1][jj];
            __nv_bfloat16 ha, la, hb, lb;
            split1(va, ha, la); split1(vb, hb, lb);
            long o = (long)(j0 + jj) * K_DIM + k0 + 2 * tx;
            uint32_t hv = (uint32_t)__bfloat16_as_ushort(ha) | ((uint32_t)__bfloat16_as_ushort(hb) << 16);
            uint32_t lv = (uint32_t)__bfloat16_as_ushort(la) | ((uint32_t)__bfloat16_as_ushort(lb) << 16);
            *(uint32_t*)((unsigned short*)g_wh + o) = hv;
            *(uint32_t*)((unsigned short*)g_wl + o) = lv;
        }
    } else {
        // ---- probs + bias fold: probs[j] = (1/K) * prod cos^2(E[d,j,g]) ----
        int j = (b - PREP_X_BLOCKS - PREP_W_BLOCKS) * 256 + tid;
        if (j < M_DIM) {
            float p = 1.0f;
#pragma unroll
            for (int d = 0; d < 9; d++)
#pragma unroll
                for (int g = 0; g < 3; g++) {
                    float a = E[(long)d * K_DIM * M_DIM + (long)j * M_DIM + g];
                    float c = cosf(a);
                    p *= c * c;
                }
            g_bias[j] = cb[j] + p * (1.0f / (float)K_DIM);
        }
    }
}

#if !USE_TC
// ---------------- hmma tile loader (fallback pass only) ----------------
DEV_INLINE void load_tile_mm(uint32_t smem_base, int stage, int kt, int tileM, int tileN, int tid) {
    uint32_t sb = smem_base + TILE_BASE + stage * MM_STAGE;
#pragma unroll
    for (int i = tid; i < 3072; i += THREADS) {
        if (i < 1024) {
            int hl = i >> 9;
            int t = i & 511; int r = t >> 2, c = t & 3;
            uint32_t dst = sb + hl * MM_A_BYTES + r * MM_ROWB + c * 16;
            long src = (long)(tileM * BM + r) * (K_DIM * 2) + (long)kt * (MM_BK * 2) + c * 16;
            cp16(dst, (const char*)(hl ? (const void*)g_xl : (const void*)g_xh) + src);
        } else {
            int j = i - 1024; int hl = j >> 10;
            int t = j & 1023; int r = t >> 2, c = t & 3;
            uint32_t dst = sb + 2 * MM_A_BYTES + hl * MM_B_BYTES + r * MM_ROWB + c * 16;
            long src = (long)(tileN * BN + r) * (K_DIM * 2) + (long)kt * (MM_BK * 2) + c * 16;
            cp16(dst, (const char*)(hl ? (const void*)g_wl : (const void*)g_wh) + src);
        }
    }
    cp_commit();
}
#endif

// ---------------- main GEMM: warp-specialized TMA + tcgen05, 256x256 single-CTA tile ----------------
__global__ void __launch_bounds__(THREADS, 1)
gemm_kernel(float* __restrict__ out,
            const __grid_constant__ CUtensorMap mAh,
            const __grid_constant__ CUtensorMap mAl,
            const __grid_constant__ CUtensorMap mBh,
            const __grid_constant__ CUtensorMap mBl) {
    extern __shared__ char smem[];
    uint32_t smem_base = smem_u32(smem);
    int tid = threadIdx.x;
    int wid = tid >> 5, lid = tid & 31;
    int bid = blockIdx.x;

#if USE_TC
    // ================= tcgen05 path: 256x256 tile, 12 M128N256K16 MMAs/iter =================
    int tileM = bid & 15;        // 16 tileM values; consecutive bids share tileN band
    int tileN = bid >> 4;        // 0..7

    if (wid == 0) TCGEN05_ALLOC(smem_base + SMEM_TMEM_PTR, 512);
    if (tid == 0) {
#pragma unroll
        for (int s = 0; s < NSTAGE; ++s) {
            MBAR_INIT(smem_base + SMEM_FULL(s), 1);   // arrive: producer expect_tx
            MBAR_INIT(smem_base + SMEM_DONE(s), 1);   // arrive: MMA commit
        }
        MBAR_INIT(smem_base + SMEM_FINAL, 1);
    }
    __syncthreads();
    uint32_t tmem;
    asm volatile("ld.shared.b32 %0, [%1];" : "=r"(tmem) : "r"(smem_base + SMEM_TMEM_PTR));

    uint32_t epred = elect_one();

    if (wid == 1 && epred) {
        // ---- producer: 4 TMAs per stage (256-row boxes), paced by MMA completion ----
        int arow = tileM * CM;
        int brow = tileN * CN;
        for (int kt = 0; kt < TC_NT; ++kt) {
            int s = kt % NSTAGE;
            uint32_t fb = smem_base + SMEM_FULL(s);
            if (kt >= NSTAGE)
                mbar_wait(smem_base + SMEM_DONE(s), ((kt - NSTAGE) / NSTAGE) & 1);
            MBAR_EXPECT_TX(fb, STAGE_BYTES);
            uint32_t sa = smem_base + TILE_BASE + s * STAGE_BYTES;
            int kx = kt * TC_BK;
            tma2d(sa + STG_AH, &mAh, kx, arow, fb);
            tma2d(sa + STG_AL, &mAl, kx, arow, fb);
            tma2d(sa + STG_BH, &mBh, kx, brow, fb);
            tma2d(sa + STG_BL, &mBl, kx, brow, fb);
        }
    } else if (wid == 0 && epred) {
        // ---- consumer: 12 MMAs per stage (2 mh x 2 ks x 3 products, N=256) ----
        for (int kt = 0; kt < TC_NT; ++kt) {
            int s = kt % NSTAGE;
            mbar_wait(smem_base + SMEM_FULL(s), (kt / NSTAGE) & 1);

            uint32_t sa  = smem_base + TILE_BASE + s * STAGE_BYTES;
            uint64_t dah = make_desc64(sa + STG_AH);
            uint64_t dal = make_desc64(sa + STG_AL);
            uint64_t dbh = make_desc64(sa + STG_BH);
            uint64_t dbl = make_desc64(sa + STG_BL);
#pragma unroll
            for (int mh = 0; mh < 2; ++mh) {               // M halves (128 rows each)
                uint64_t am = (uint64_t)(mh * 512);        // 128 rows * 64B = 8KB = 512 units
                uint32_t dd = tmem + mh * 256;             // 256 cols per M-half
#pragma unroll
                for (int ks = 0; ks < 2; ++ks) {           // K=16 per MMA, 2 steps (BK=32)
                    uint64_t o = (uint64_t)(ks * 2);       // 32B = 2 desc units
                    uint32_t acc = (kt > 0) || (ks > 0);
                    mma_bf16_ss(dd, dah + am + o, dbh + o, acc);  // hi*hi
                    mma_bf16_ss(dd, dah + am + o, dbl + o, 1u);   // hi*lo
                    mma_bf16_ss(dd, dal + am + o, dbh + o, 1u);   // lo*hi
                }
            }
            TCGEN05_COMMIT(smem_base + SMEM_DONE(s));
        }
        TCGEN05_COMMIT(smem_base + SMEM_FINAL);        // tracks ALL prior MMAs
    }

    // Everyone: wait for all MMAs (count=1, first phase).
    mbar_wait(smem_base + SMEM_FINAL, 0);
    TCGEN05_FENCE_AFTER();

    // Epilogue: 16 warps. wid>>3 = M-half; (wid&7): &3 = subpartition, >>2 = col half.
    // Each warp: 32 lanes x 128 cols (4x LD_X32).
    {
        int mh   = wid >> 3;
        int wg   = wid & 7;
        int sub  = wg & 3;
        int ch   = wg >> 2;
        long gm  = (long)tileM * CM + mh * 128 + sub * 32 + lid;
#pragma unroll
        for (int cc = 0; cc < 4; ++cc) {
            uint32_t d[32];
            TCGEN05_LD_X32(d, tmem + mh * 256 + ch * 128 + cc * 32);
            TCGEN05_WAIT_LD();
            int gc = tileN * CN + ch * 128 + cc * 32;
            const float4* bp = (const float4*)(g_bias + gc);
            float4* op = (float4*)(out + gm * M_DIM + gc);
#pragma unroll
            for (int q = 0; q < 8; ++q) {
                float4 b = bp[q];
                float4 o;
                o.x = tanhf(__uint_as_float(d[q * 4 + 0]) + b.x);
                o.y = tanhf(__uint_as_float(d[q * 4 + 1]) + b.y);
                o.z = tanhf(__uint_as_float(d[q * 4 + 2]) + b.z);
                o.w = tanhf(__uint_as_float(d[q * 4 + 3]) + b.w);
                op[q] = o;
            }
        }
        TCGEN05_FENCE_BEFORE();
    }

    __syncthreads();
    if (tid == 0) {
#pragma unroll
        for (int s = 0; s < NSTAGE; ++s) {
            MBAR_INVAL(smem_base + SMEM_FULL(s));
            MBAR_INVAL(smem_base + SMEM_DONE(s));
        }
        MBAR_INVAL(smem_base + SMEM_FINAL);
    }
    __syncthreads();
    if (wid == 0) TCGEN05_DEALLOC(tmem, 512);

#else
    // ================= HMMA fallback (base-PTX legal; never runs on GB300) =================
    // CTA covers 256x256 as two sequential 128x256 halves.
    int tileN = bid >> 4;
    int wr = wid & 3;
    int wc = wid >> 2;
    const int lrow = lid & 15;
    const int lk16b = (lid >> 4) * 16;

    for (int mh = 0; mh < 2; ++mh) {
        int tileM = (bid & 15) * 2 + mh;

        float acc[2][8][4];
#pragma unroll
        for (int mt = 0; mt < 2; ++mt)
#pragma unroll
            for (int nt = 0; nt < 8; ++nt)
#pragma unroll
                for (int q = 0; q < 4; ++q) acc[mt][nt][q] = 0.0f;

        load_tile_mm(smem_base, 0, 0, tileM, tileN, tid);
        load_tile_mm(smem_base, 1, 1, tileM, tileN, tid);
        load_tile_mm(smem_base, 2, 2, tileM, tileN, tid);

        for (int kt = 0; kt < MM_NT; ++kt) {
            asm volatile("cp.async.wait_group 2;" ::: "memory");
            __syncthreads();

            int s = kt % MM_STAGES;
            uint32_t sb  = smem_base + TILE_BASE + s * MM_STAGE;
            uint32_t sAh = sb;
            uint32_t sAl = sb + MM_A_BYTES;
            uint32_t sBh = sb + 2 * MM_A_BYTES;
            uint32_t sBl = sb + 2 * MM_A_BYTES + MM_B_BYTES;

#pragma unroll
            for (int k16 = 0; k16 < 2; ++k16) {
                uint32_t koff = k16 * 32 + lk16b;
                uint32_t aoff = (uint32_t)(wr * 32 + lrow) * MM_ROWB + koff;
                uint32_t boff = (uint32_t)(wc * 64 + lrow) * MM_ROWB + koff;

                uint32_t ah[2][4], bh[4][4];
                ldsm4(ah[0], sAh + aoff);
                ldsm4(ah[1], sAh + aoff + 16 * MM_ROWB);
#pragma unroll
                for (int g = 0; g < 4; ++g) ldsm4(bh[g], sBh + boff + g * 16 * MM_ROWB);

#pragma unroll
                for (int mt = 0; mt < 2; ++mt)
#pragma unroll
                    for (int nt = 0; nt < 8; ++nt)
                        mma16816(acc[mt][nt], ah[mt], bh[nt >> 1][nt & 1], bh[nt >> 1][(nt & 1) + 2]);

                uint32_t al[2][4];
                ldsm4(al[0], sAl + aoff);
                ldsm4(al[1], sAl + aoff + 16 * MM_ROWB);
#pragma unroll
                for (int mt = 0; mt < 2; ++mt)
#pragma unroll
                    for (int nt = 0; nt < 8; ++nt)
                        mma16816(acc[mt][nt], al[mt], bh[nt >> 1][nt & 1], bh[nt >> 1][(nt & 1) + 2]);

                uint32_t bl[4][4];
#pragma unroll
                for (int g = 0; g < 4; ++g) ldsm4(bl[g], sBl + boff + g * 16 * MM_ROWB);
#pragma unroll
                for (int mt = 0; mt < 2; ++mt)
#pragma unroll
                    for (int nt = 0; nt < 8; ++nt)
                        mma16816(acc[mt][nt], ah[mt], bl[nt >> 1][nt & 1], bl[nt >> 1][(nt & 1) + 2]);
            }

            __syncthreads();
            if (kt + MM_STAGES < MM_NT)
                load_tile_mm(smem_base, s, kt + MM_STAGES, tileM, tileN, tid);
        }

        {
            int r0 = tileM * BM + wr * 32 + (lid >> 2);
            int c0 = tileN * BN + wc * 64 + (lid & 3) * 2;
#pragma unroll
            for (int mt = 0; mt < 2; ++mt) {
#pragma unroll
                for (int nt = 0; nt < 8; ++nt) {
                    int row = r0 + mt * 16;
                    int col = c0 + nt * 8;
                    float2 bv = *(const float2*)(g_bias + col);
                    float2 o0, o1;
                    o0.x = tanhf(acc[mt][nt][0] + bv.x);
                    o0.y = tanhf(acc[mt][nt][1] + bv.y);
                    o1.x = tanhf(acc[mt][nt][2] + bv.x);
                    o1.y = tanhf(acc[mt][nt][3] + bv.y);
                    *(float2*)(out + (long)row * M_DIM + col) = o0;
                    *(float2*)(out + (long)(row + 8) * M_DIM + col) = o1;
                }
            }
        }
        __syncthreads();
    }
#endif
}

// ---------------- host: tensormap creation via driver entry point ----------------
typedef CUresult (*EncodeTiledFn)(
    CUtensorMap*, CUtensorMapDataType, cuuint32_t, void*,
    const cuuint64_t*, const cuuint64_t*, const cuuint32_t*, const cuuint32_t*,
    CUtensorMapInterleave, CUtensorMapSwizzle, CUtensorMapL2promotion, CUtensorMapFloatOOBfill);

static void make_map(EncodeTiledFn enc, CUtensorMap* m, void* base,
                     unsigned long long rows, unsigned box_rows) {
    cuuint64_t dims[2]    = {(cuuint64_t)K_DIM, (cuuint64_t)rows};
    cuuint64_t strides[1] = {(cuuint64_t)K_DIM * 2};           // bytes between rows
    cuuint32_t box[2]     = {32, box_rows};                    // 64B x box_rows (SW64)
    cuuint32_t es[2]      = {1, 1};
    enc(m, CU_TENSOR_MAP_DATA_TYPE_BFLOAT16, 2, base, dims, strides, box, es,
        CU_TENSOR_MAP_INTERLEAVE_NONE, CU_TENSOR_MAP_SWIZZLE_64B,
        CU_TENSOR_MAP_L2_PROMOTION_L2_128B, CU_TENSOR_MAP_FLOAT_OOB_FILL_NONE);
}

extern "C" void kernel_launch(void* const* d_in, const int* in_sizes, int n_in,
                              void* d_out, int out_size) {
    const float* x  = (const float*)d_in[0];
    const float* E  = (const float*)d_in[1];
    // d_in[2] = eternal_biases: unused by the reference as well
    const float* W  = (const float*)d_in[3];
    const float* cb = (const float*)d_in[4];
    float* out = (float*)d_out;

    // tensormaps (host-side; recreated per call — deterministic, no device work)
    EncodeTiledFn enc = nullptr;
    cudaDriverEntryPointQueryResult qr;
    cudaGetDriverEntryPointByVersion("cuTensorMapEncodeTiled", (void**)&enc, 12000,
                                     cudaEnableDefault, &qr);
    void *pxh, *pxl, *pwh, *pwl;
    cudaGetSymbolAddress(&pxh, g_xh);
    cudaGetSymbolAddress(&pxl, g_xl);
    cudaGetSymbolAddress(&pwh, g_wh);
    cudaGetSymbolAddress(&pwl, g_wl);
    CUtensorMap mAh, mAl, mBh, mBl;
    make_map(enc, &mAh, pxh, B_DIM, 256);   // A: 256-row boxes
    make_map(enc, &mAl, pxl, B_DIM, 256);
    make_map(enc, &mBh, pwh, M_DIM, 256);   // B: 256-row boxes
    make_map(enc, &mBl, pwl, M_DIM, 256);

    cudaFuncSetAttribute(gemm_kernel, cudaFuncAttributeMaxDynamicSharedMemorySize, SMEM_TOTAL);

    prep_kernel<<<PREP_X_BLOCKS + PREP_W_BLOCKS + PREP_P_BLOCKS, 256>>>(x, W, E, cb);
    gemm_kernel<<<(B_DIM / CM) * (M_DIM / CN), THREADS, SMEM_TOTAL>>>(out, mAh, mAl, mBh, mBl);
}